// round 5
// baseline (speedup 1.0000x reference)
#include <cuda_runtime.h>
#include <cuda_bf16.h>
#include <cstdint>

// Problem constants (fixed by the dataset)
#define BB 8
#define CC 512
#define NN 4096
#define DD 64
#define K2_NS 8   // n-splits for k2

// Scratch (static device globals — no allocation)
__device__ float g_Qf[BB][DD][NN];          // delu(Q)  8 MB
__device__ float g_Kf[BB][DD][NN];          // delu(K)  8 MB
__device__ float g_Mp[K2_NS][BB][CC][DD];   // partial M^T: [ns][b][c][d]
__device__ float g_KVp[4][BB][DD][CC];      // partial KV (c-splits)
__device__ float g_KV[BB][DD][CC];          // KV = M @ wv^T + Ksum (x) bv
__device__ float g_Ksum[BB][DD];

__device__ __forceinline__ float delu_f(float v) {
    return 10.0f * fmaxf(v, 0.0f) + __expf(10.0f * fminf(v, 0.0f));
}

__device__ __forceinline__ uint32_t smem_u32(const void* p) {
    uint32_t a;
    asm("{ .reg .u64 t; cvta.to.shared.u64 t, %1; cvt.u32.u64 %0, t; }"
        : "=r"(a) : "l"(p));
    return a;
}

#define CP16(dst, src) \
    asm volatile("cp.async.cg.shared.global [%0], [%1], 16;" :: "r"(dst), "l"(src))
#define CP_COMMIT() asm volatile("cp.async.commit_group;" ::: "memory")
#define CP_WAIT1()  asm volatile("cp.async.wait_group 1;" ::: "memory")
#define CP_WAIT0()  asm volatile("cp.async.wait_group 0;" ::: "memory")

// D += A(16x8) * B(8x8), tf32 inputs (fp32 bits, HW-truncated), f32 accum
__device__ __forceinline__ void mma_tf32(float4& d,
                                         uint32_t a0, uint32_t a1, uint32_t a2, uint32_t a3,
                                         uint32_t b0, uint32_t b1) {
    asm volatile(
        "mma.sync.aligned.m16n8k8.row.col.f32.tf32.tf32.f32 "
        "{%0,%1,%2,%3}, {%4,%5,%6,%7}, {%8,%9}, {%0,%1,%2,%3};"
        : "+f"(d.x), "+f"(d.y), "+f"(d.z), "+f"(d.w)
        : "r"(a0), "r"(a1), "r"(a2), "r"(a3), "r"(b0), "r"(b1));
}

// ---------------------------------------------------------------------------
// K1 (mma + cp.async 2-stage): [Wq;Wk](128x512) @ x[b](512x4096) + bias, delu
// ---------------------------------------------------------------------------
#define K1_ABUF (128 * 36)
#define K1_BBUF (32 * 136)
#define K1_SMEM ((2 * K1_ABUF + 2 * K1_BBUF) * 4)

__global__ __launch_bounds__(256) void k1_qk(
    const float* __restrict__ x,
    const float* __restrict__ wq, const float* __restrict__ bq,
    const float* __restrict__ wk, const float* __restrict__ bk)
{
    const int b  = blockIdx.y;
    const int n0 = blockIdx.x * 128;
    const int tid = threadIdx.x;
    const int wid = tid >> 5, lane = tid & 31;
    const int g = lane >> 2, tig = lane & 3;
    const int wm0 = (wid >> 1) * 32;
    const int wn0 = (wid & 1) * 64;

    extern __shared__ float dsm[];
    float* sA = dsm;
    float* sB = dsm + 2 * K1_ABUF;
    const uint32_t sA_addr = smem_u32(sA);
    const uint32_t sB_addr = smem_u32(sB);
    const uint32_t* sAu = reinterpret_cast<const uint32_t*>(sA);
    const uint32_t* sBu = reinterpret_cast<const uint32_t*>(sB);

    float4 acc[2][8];
#pragma unroll
    for (int i = 0; i < 2; i++)
#pragma unroll
        for (int j = 0; j < 8; j++) acc[i][j] = make_float4(0.f, 0.f, 0.f, 0.f);

#define K1_ISSUE(ch) do {                                                        \
    const int k0_ = (ch) * 32; const int buf_ = (ch) & 1;                        \
    _Pragma("unroll")                                                            \
    for (int i = 0; i < 4; i++) {                                                \
        int idx = tid + i * 256;                                                 \
        int r = idx >> 3; int kk = (idx & 7) << 2;                               \
        const float* src = (r < 64) ? (wq + (size_t)r * CC + k0_ + kk)           \
                                    : (wk + (size_t)(r - 64) * CC + k0_ + kk);   \
        CP16(sA_addr + (uint32_t)(buf_ * K1_ABUF + r * 36 + kk) * 4, src);       \
    }                                                                            \
    _Pragma("unroll")                                                            \
    for (int i = 0; i < 4; i++) {                                                \
        int idx = tid + i * 256;                                                 \
        int kk = idx >> 5; int j = (idx & 31) << 2;                              \
        const float* src = x + ((size_t)(b * CC + k0_ + kk)) * NN + n0 + j;      \
        CP16(sB_addr + (uint32_t)(buf_ * K1_BBUF + kk * 136 + j) * 4, src);      \
    }                                                                            \
    CP_COMMIT();                                                                 \
} while (0)

    K1_ISSUE(0);
    for (int ch = 0; ch < 16; ch++) {
        if (ch < 15) { K1_ISSUE(ch + 1); CP_WAIT1(); } else { CP_WAIT0(); }
        __syncthreads();
        const uint32_t* A = sAu + (ch & 1) * K1_ABUF;
        const uint32_t* Bm = sBu + (ch & 1) * K1_BBUF;
#pragma unroll
        for (int ks = 0; ks < 32; ks += 8) {
            uint32_t a[2][4];
#pragma unroll
            for (int i = 0; i < 2; i++) {
                int r = wm0 + i * 16 + g;
                a[i][0] = A[r * 36 + ks + tig];
                a[i][1] = A[(r + 8) * 36 + ks + tig];
                a[i][2] = A[r * 36 + ks + tig + 4];
                a[i][3] = A[(r + 8) * 36 + ks + tig + 4];
            }
#pragma unroll
            for (int j = 0; j < 8; j++) {
                int n = wn0 + j * 8 + g;
                uint32_t b0 = Bm[(ks + tig) * 136 + n];
                uint32_t b1 = Bm[(ks + tig + 4) * 136 + n];
#pragma unroll
                for (int i = 0; i < 2; i++)
                    mma_tf32(acc[i][j], a[i][0], a[i][1], a[i][2], a[i][3], b0, b1);
            }
        }
        __syncthreads();
    }

    // epilogue: bias + delu -> Qf / Kf
#pragma unroll
    for (int i = 0; i < 2; i++) {
        int r0 = wm0 + i * 16 + g;
        int r1 = r0 + 8;
        float bias0 = (r0 < 64) ? bq[r0] : bk[r0 - 64];
        float bias1 = (r1 < 64) ? bq[r1] : bk[r1 - 64];
        float* dst0 = (r0 < 64) ? &g_Qf[b][r0][0] : &g_Kf[b][r0 - 64][0];
        float* dst1 = (r1 < 64) ? &g_Qf[b][r1][0] : &g_Kf[b][r1 - 64][0];
#pragma unroll
        for (int j = 0; j < 8; j++) {
            int n = n0 + wn0 + j * 8 + 2 * tig;
            float2 o0 = make_float2(delu_f(acc[i][j].x + bias0), delu_f(acc[i][j].y + bias0));
            float2 o1 = make_float2(delu_f(acc[i][j].z + bias1), delu_f(acc[i][j].w + bias1));
            *reinterpret_cast<float2*>(dst0 + n) = o0;
            *reinterpret_cast<float2*>(dst1 + n) = o1;
        }
    }
}

// ---------------------------------------------------------------------------
// K2a: Ksum[b][d] = sum_n Kf[b][d][n]
// ---------------------------------------------------------------------------
__global__ __launch_bounds__(256) void k2a_ksum()
{
    const int d = blockIdx.x, b = blockIdx.y;
    const float* src = &g_Kf[b][d][0];
    float s = 0.f;
    for (int i = threadIdx.x; i < NN; i += 256) s += src[i];
#pragma unroll
    for (int o = 16; o > 0; o >>= 1) s += __shfl_xor_sync(0xffffffffu, s, o);
    __shared__ float red[8];
    if ((threadIdx.x & 31) == 0) red[threadIdx.x >> 5] = s;
    __syncthreads();
    if (threadIdx.x == 0) {
        float t = 0.f;
#pragma unroll
        for (int w = 0; w < 8; w++) t += red[w];
        g_Ksum[b][d] = t;
    }
}

// ---------------------------------------------------------------------------
// K2 (mma + cp.async 2-stage): Mp[ns][b][c][d] = sum_n x[b][c][n]*Kf[b][d][n]
// ---------------------------------------------------------------------------
#define K2_XBUF (128 * 36)
#define K2_KBUF (64 * 36)
#define K2_SMEM ((2 * K2_XBUF + 2 * K2_KBUF) * 4)

__global__ __launch_bounds__(256) void k2_mma(const float* __restrict__ x)
{
    const int b  = blockIdx.y;
    const int c0 = blockIdx.x * 128;
    const int ns = blockIdx.z;
    const int nbase = ns * (NN / K2_NS);       // 512 per split
    const int tid = threadIdx.x;
    const int wid = tid >> 5, lane = tid & 31;
    const int g = lane >> 2, tig = lane & 3;
    const int wc0 = (wid >> 1) * 32;
    const int wd0 = (wid & 1) * 32;

    extern __shared__ float dsm[];
    float* sX = dsm;
    float* sK = dsm + 2 * K2_XBUF;
    const uint32_t sX_addr = smem_u32(sX);
    const uint32_t sK_addr = smem_u32(sK);
    const uint32_t* sXu = reinterpret_cast<const uint32_t*>(sX);
    const uint32_t* sKu = reinterpret_cast<const uint32_t*>(sK);

    float4 acc[2][4];
#pragma unroll
    for (int i = 0; i < 2; i++)
#pragma unroll
        for (int j = 0; j < 4; j++) acc[i][j] = make_float4(0.f, 0.f, 0.f, 0.f);

#define K2_ISSUE(ch) do {                                                        \
    const int nb_ = nbase + (ch) * 32; const int buf_ = (ch) & 1;                \
    _Pragma("unroll")                                                            \
    for (int i = 0; i < 4; i++) {                                                \
        int idx = tid + i * 256;                                                 \
        int r = idx >> 3; int kk = (idx & 7) << 2;                               \
        const float* src = x + ((size_t)(b * CC + c0 + r)) * NN + nb_ + kk;      \
        CP16(sX_addr + (uint32_t)(buf_ * K2_XBUF + r * 36 + kk) * 4, src);       \
    }                                                                            \
    _Pragma("unroll")                                                            \
    for (int i = 0; i < 2; i++) {                                                \
        int idx = tid + i * 256;                                                 \
        int r = idx >> 3; int kk = (idx & 7) << 2;                               \
        const float* src = &g_Kf[b][r][nb_ + kk];                                \
        CP16(sK_addr + (uint32_t)(buf_ * K2_KBUF + r * 36 + kk) * 4, src);       \
    }                                                                            \
    CP_COMMIT();                                                                 \
} while (0)

    K2_ISSUE(0);
    for (int ch = 0; ch < 16; ch++) {
        if (ch < 15) { K2_ISSUE(ch + 1); CP_WAIT1(); } else { CP_WAIT0(); }
        __syncthreads();
        const uint32_t* X = sXu + (ch & 1) * K2_XBUF;
        const uint32_t* Km = sKu + (ch & 1) * K2_KBUF;
#pragma unroll
        for (int ks = 0; ks < 32; ks += 8) {
            uint32_t a[2][4];
#pragma unroll
            for (int i = 0; i < 2; i++) {
                int r = wc0 + i * 16 + g;
                a[i][0] = X[r * 36 + ks + tig];
                a[i][1] = X[(r + 8) * 36 + ks + tig];
                a[i][2] = X[r * 36 + ks + tig + 4];
                a[i][3] = X[(r + 8) * 36 + ks + tig + 4];
            }
#pragma unroll
            for (int j = 0; j < 4; j++) {
                int d = wd0 + j * 8 + g;
                uint32_t b0 = Km[d * 36 + ks + tig];
                uint32_t b1 = Km[d * 36 + ks + tig + 4];
#pragma unroll
                for (int i = 0; i < 2; i++)
                    mma_tf32(acc[i][j], a[i][0], a[i][1], a[i][2], a[i][3], b0, b1);
            }
        }
        __syncthreads();
    }
#pragma unroll
    for (int i = 0; i < 2; i++) {
        int r0 = c0 + wc0 + i * 16 + g;
#pragma unroll
        for (int j = 0; j < 4; j++) {
            int d = wd0 + j * 8 + 2 * tig;
            *reinterpret_cast<float2*>(&g_Mp[ns][b][r0][d])     = make_float2(acc[i][j].x, acc[i][j].y);
            *reinterpret_cast<float2*>(&g_Mp[ns][b][r0 + 8][d]) = make_float2(acc[i][j].z, acc[i][j].w);
        }
    }
}

// ---------------------------------------------------------------------------
// K3 (mma): KVp[cs][b][m][e] = sum_{c in 128-split} (sum_ns Mp[ns][b][c][m]) * wv[e][c]
// grid (4 e-tiles, 8 b, 4 cs) = 128 blocks, 256 thr. Tile 64m x 128e, K-chunk 32.
// ---------------------------------------------------------------------------
__global__ __launch_bounds__(256) void k3_mma(const float* __restrict__ wv)
{
    const int b  = blockIdx.y;
    const int e0 = blockIdx.x * 128;
    const int cs = blockIdx.z;
    const int cb0 = cs * 128;
    const int tid = threadIdx.x;
    const int wid = tid >> 5, lane = tid & 31;
    const int g = lane >> 2, tig = lane & 3;
    const int wm0 = (wid >> 2) * 32;   // 2 m-warps
    const int we0 = (wid & 3) * 32;    // 4 e-warps

    __shared__ float sM[32 * 72];      // [c][m] stride 72
    __shared__ float sW[128 * 36];     // [e][c] stride 36
    const uint32_t* sMu = reinterpret_cast<const uint32_t*>(sM);
    const uint32_t* sWu = reinterpret_cast<const uint32_t*>(sW);

    float4 acc[2][4];
#pragma unroll
    for (int i = 0; i < 2; i++)
#pragma unroll
        for (int j = 0; j < 4; j++) acc[i][j] = make_float4(0.f, 0.f, 0.f, 0.f);

    for (int cc = 0; cc < 128; cc += 32) {
        const int ca = cb0 + cc;
        // Msum tile (fold 8 Mp partials): 32 c x 64 m = 512 float4
#pragma unroll
        for (int i = 0; i < 2; i++) {
            int idx = tid + i * 256;
            int c = idx >> 4;
            int m = (idx & 15) << 2;
            float4 s = make_float4(0.f, 0.f, 0.f, 0.f);
#pragma unroll
            for (int ns = 0; ns < K2_NS; ns++) {
                float4 v = *reinterpret_cast<const float4*>(&g_Mp[ns][b][ca + c][m]);
                s.x += v.x; s.y += v.y; s.z += v.z; s.w += v.w;
            }
            *reinterpret_cast<float4*>(&sM[c * 72 + m]) = s;
        }
        // wv tile: 128 e x 32 c = 1024 float4
#pragma unroll
        for (int i = 0; i < 4; i++) {
            int idx = tid + i * 256;
            int e = idx >> 3;
            int k = (idx & 7) << 2;
            float4 v = *reinterpret_cast<const float4*>(
                wv + (size_t)(e0 + e) * CC + ca + k);
            *reinterpret_cast<float4*>(&sW[e * 36 + k]) = v;
        }
        __syncthreads();
#pragma unroll
        for (int ks = 0; ks < 32; ks += 8) {
            uint32_t a[2][4];
#pragma unroll
            for (int i = 0; i < 2; i++) {
                int r = wm0 + i * 16 + g;
                a[i][0] = sMu[(ks + tig) * 72 + r];
                a[i][1] = sMu[(ks + tig) * 72 + r + 8];
                a[i][2] = sMu[(ks + tig + 4) * 72 + r];
                a[i][3] = sMu[(ks + tig + 4) * 72 + r + 8];
            }
#pragma unroll
            for (int j = 0; j < 4; j++) {
                int e = we0 + j * 8 + g;
                uint32_t b0 = sWu[e * 36 + ks + tig];
                uint32_t b1 = sWu[e * 36 + ks + tig + 4];
#pragma unroll
                for (int i = 0; i < 2; i++)
                    mma_tf32(acc[i][j], a[i][0], a[i][1], a[i][2], a[i][3], b0, b1);
            }
        }
        __syncthreads();
    }
#pragma unroll
    for (int i = 0; i < 2; i++) {
        int m0 = wm0 + i * 16 + g;
#pragma unroll
        for (int j = 0; j < 4; j++) {
            int e = e0 + we0 + j * 8 + 2 * tig;
            *reinterpret_cast<float2*>(&g_KVp[cs][b][m0][e])     = make_float2(acc[i][j].x, acc[i][j].y);
            *reinterpret_cast<float2*>(&g_KVp[cs][b][m0 + 8][e]) = make_float2(acc[i][j].z, acc[i][j].w);
        }
    }
}

// ---------------------------------------------------------------------------
// K3c: KV = sum_cs KVp + Ksum (x) bv.  64K float4; grid 256 x 256
// ---------------------------------------------------------------------------
__global__ __launch_bounds__(256) void k3c_merge(const float* __restrict__ bv)
{
    const int f = blockIdx.x * 256 + threadIdx.x;
    const int b = f >> 13;
    const int r = f & 8191;
    const int m = r >> 7;
    const int e4 = (r & 127) << 2;

    float4 s0 = *reinterpret_cast<const float4*>(&g_KVp[0][b][m][e4]);
    float4 s1 = *reinterpret_cast<const float4*>(&g_KVp[1][b][m][e4]);
    float4 s2 = *reinterpret_cast<const float4*>(&g_KVp[2][b][m][e4]);
    float4 s3 = *reinterpret_cast<const float4*>(&g_KVp[3][b][m][e4]);
    float4 bb = *reinterpret_cast<const float4*>(bv + e4);
    const float ks = g_Ksum[b][m];
    float4 o;
    o.x = s0.x + s1.x + s2.x + s3.x + ks * bb.x;
    o.y = s0.y + s1.y + s2.y + s3.y + ks * bb.y;
    o.z = s0.z + s1.z + s2.z + s3.z + ks * bb.z;
    o.w = s0.w + s1.w + s2.w + s3.w + ks * bb.w;
    *reinterpret_cast<float4*>(&g_KV[b][m][e4]) = o;
}

// ---------------------------------------------------------------------------
// K4 (mma + cp.async prefetch): out = x + gamma * norm[n] * (Qf^T @ KV)^T
// grid (4 c-tiles, 32 n-tiles, 8 b) — c fastest for Qf L2 reuse.
// dyn smem: sQ[64][136] + sV[64][136] + sX[128][128]
// ---------------------------------------------------------------------------
#define K4_QV (64 * 136)
#define K4_SMEM ((2 * K4_QV + 128 * 128) * 4)

__global__ __launch_bounds__(256) void k4_out(
    const float* __restrict__ x, const float* __restrict__ gamma,
    float* __restrict__ out)
{
    const int b  = blockIdx.z;
    const int c0 = blockIdx.x * 128;
    const int n0 = blockIdx.y * 128;
    const int tid = threadIdx.x;
    const int wid = tid >> 5, lane = tid & 31;
    const int g = lane >> 2, tig = lane & 3;
    const int wc0 = (wid >> 1) * 32;
    const int wn0 = (wid & 1) * 64;

    extern __shared__ float smem[];
    float* sQ = smem;                  // [d][n] stride 136
    float* sV = smem + K4_QV;          // [d][c] stride 136
    float* sX = smem + 2 * K4_QV;      // [c][n] 128x128
    const uint32_t sQ_addr = smem_u32(sQ);
    const uint32_t sV_addr = smem_u32(sV);
    const uint32_t sX_addr = smem_u32(sX);
    const uint32_t* sQu = reinterpret_cast<const uint32_t*>(sQ);
    const uint32_t* sVu = reinterpret_cast<const uint32_t*>(sV);
    __shared__ float snorm[128];
    __shared__ float sKs[64];

    // group 0: Qf + KV tiles
#pragma unroll
    for (int i = 0; i < 8; i++) {
        int idx = tid + i * 256;
        int d = idx >> 5;
        int j = (idx & 31) << 2;
        CP16(sQ_addr + (uint32_t)(d * 136 + j) * 4, &g_Qf[b][d][n0 + j]);
    }
#pragma unroll
    for (int i = 0; i < 8; i++) {
        int idx = tid + i * 256;
        int d = idx >> 5;
        int j = (idx & 31) << 2;
        CP16(sV_addr + (uint32_t)(d * 136 + j) * 4, &g_KV[b][d][c0 + j]);
    }
    CP_COMMIT();
    // group 1: x tile (consumed only in epilogue)
#pragma unroll
    for (int i = 0; i < 16; i++) {
        int idx = tid + i * 256;
        int c = idx >> 5;
        int j = (idx & 31) << 2;
        CP16(sX_addr + (uint32_t)(c * 128 + j) * 4,
             x + ((size_t)(b * CC + c0 + c)) * NN + n0 + j);
    }
    CP_COMMIT();

    if (tid < 64) sKs[tid] = g_Ksum[b][tid] + 1e-10f;
    CP_WAIT1();            // Qf + KV ready; x still in flight
    __syncthreads();

    if (tid < 128) {
        float s = 0.f;
#pragma unroll
        for (int d = 0; d < 64; d++) s += sQ[d * 136 + tid] * sKs[d];
        snorm[tid] = 1.0f / s;
    }
    __syncthreads();

    float4 acc[2][8];
#pragma unroll
    for (int i = 0; i < 2; i++)
#pragma unroll
        for (int j = 0; j < 8; j++) acc[i][j] = make_float4(0.f, 0.f, 0.f, 0.f);

#pragma unroll
    for (int ks = 0; ks < 64; ks += 8) {
        uint32_t a[2][4];
#pragma unroll
        for (int i = 0; i < 2; i++) {
            int r = wc0 + i * 16 + g;
            a[i][0] = sVu[(ks + tig) * 136 + r];
            a[i][1] = sVu[(ks + tig) * 136 + r + 8];
            a[i][2] = sVu[(ks + tig + 4) * 136 + r];
            a[i][3] = sVu[(ks + tig + 4) * 136 + r + 8];
        }
#pragma unroll
        for (int j = 0; j < 8; j++) {
            int n = wn0 + j * 8 + g;
            uint32_t b0 = sQu[(ks + tig) * 136 + n];
            uint32_t b1 = sQu[(ks + tig + 4) * 136 + n];
#pragma unroll
            for (int i = 0; i < 2; i++)
                mma_tf32(acc[i][j], a[i][0], a[i][1], a[i][2], a[i][3], b0, b1);
        }
    }

    CP_WAIT0();
    __syncthreads();

    const float gm = gamma[0];
#pragma unroll
    for (int i = 0; i < 2; i++) {
        int cl0 = wc0 + i * 16 + g;
        int cl1 = cl0 + 8;
#pragma unroll
        for (int j = 0; j < 8; j++) {
            int nl = wn0 + j * 8 + 2 * tig;
            float nm0 = snorm[nl], nm1 = snorm[nl + 1];
            float2 x0 = *reinterpret_cast<const float2*>(&sX[cl0 * 128 + nl]);
            float2 x1 = *reinterpret_cast<const float2*>(&sX[cl1 * 128 + nl]);
            size_t off0 = ((size_t)b * CC + c0 + cl0) * NN + n0 + nl;
            size_t off1 = ((size_t)b * CC + c0 + cl1) * NN + n0 + nl;
            float2 o0 = make_float2(x0.x + gm * acc[i][j].x * nm0,
                                    x0.y + gm * acc[i][j].y * nm1);
            float2 o1 = make_float2(x1.x + gm * acc[i][j].z * nm0,
                                    x1.y + gm * acc[i][j].w * nm1);
            *reinterpret_cast<float2*>(out + off0) = o0;
            *reinterpret_cast<float2*>(out + off1) = o1;
        }
    }
}

// ---------------------------------------------------------------------------
extern "C" void kernel_launch(void* const* d_in, const int* in_sizes, int n_in,
                              void* d_out, int out_size)
{
    const float* x     = (const float*)d_in[0];
    const float* wq    = (const float*)d_in[1];
    const float* bq    = (const float*)d_in[2];
    const float* wk    = (const float*)d_in[3];
    const float* bk    = (const float*)d_in[4];
    const float* wv    = (const float*)d_in[5];
    const float* bv    = (const float*)d_in[6];
    const float* gamma = (const float*)d_in[7];
    float* out = (float*)d_out;

    static bool attr_set = false;
    if (!attr_set) {
        cudaFuncSetAttribute(k1_qk,  cudaFuncAttributeMaxDynamicSharedMemorySize, K1_SMEM);
        cudaFuncSetAttribute(k2_mma, cudaFuncAttributeMaxDynamicSharedMemorySize, K2_SMEM);
        cudaFuncSetAttribute(k4_out, cudaFuncAttributeMaxDynamicSharedMemorySize, K4_SMEM);
        attr_set = true;
    }

    k1_qk<<<dim3(NN / 128, BB), 256, K1_SMEM>>>(x, wq, bq, wk, bk);
    k2a_ksum<<<dim3(DD, BB), 256>>>();
    k2_mma<<<dim3(CC / 128, BB, K2_NS), 256, K2_SMEM>>>(x);
    k3_mma<<<dim3(CC / 128, BB, 4), 256>>>(wv);
    k3c_merge<<<256, 256>>>(bv);
    k4_out<<<dim3(CC / 128, NN / 128, BB), 256, K4_SMEM>>>(x, gamma, out);
}

// round 6
// speedup vs baseline: 1.0500x; 1.0500x over previous
#include <cuda_runtime.h>
#include <cuda_bf16.h>
#include <cstdint>

// Problem constants (fixed by the dataset)
#define BB 8
#define CC 512
#define NN 4096
#define DD 64
#define K2_NS 8   // n-splits for k2

// Scratch (static device globals — no allocation)
__device__ float g_Qf[BB][DD][NN];          // delu(Q)  8 MB
__device__ float g_Kf[BB][DD][NN];          // delu(K)  8 MB
__device__ float g_Mp[K2_NS][BB][CC][DD];   // partial M^T: [ns][b][c][d]
__device__ float g_Msum[BB][CC][DD];        // summed M^T (1 MB)
__device__ float g_KVp[4][BB][DD][CC];      // partial KV (c-splits)
__device__ float g_KV[BB][DD][CC];          // KV = M @ wv^T + Ksum (x) bv
__device__ float g_Ksp[32][BB][DD];         // per-n-tile Ksum partials (from k1)
__device__ float g_Ksum[BB][DD];

__device__ __forceinline__ float delu_f(float v) {
    return 10.0f * fmaxf(v, 0.0f) + __expf(10.0f * fminf(v, 0.0f));
}

__device__ __forceinline__ uint32_t smem_u32(const void* p) {
    uint32_t a;
    asm("{ .reg .u64 t; cvta.to.shared.u64 t, %1; cvt.u32.u64 %0, t; }"
        : "=r"(a) : "l"(p));
    return a;
}

#define CP16(dst, src) \
    asm volatile("cp.async.cg.shared.global [%0], [%1], 16;" :: "r"(dst), "l"(src))
#define CP_COMMIT() asm volatile("cp.async.commit_group;" ::: "memory")
#define CP_WAIT1()  asm volatile("cp.async.wait_group 1;" ::: "memory")
#define CP_WAIT0()  asm volatile("cp.async.wait_group 0;" ::: "memory")

// D += A(16x8) * B(8x8), tf32 inputs (fp32 bits, HW-truncated), f32 accum
__device__ __forceinline__ void mma_tf32(float4& d,
                                         uint32_t a0, uint32_t a1, uint32_t a2, uint32_t a3,
                                         uint32_t b0, uint32_t b1) {
    asm volatile(
        "mma.sync.aligned.m16n8k8.row.col.f32.tf32.tf32.f32 "
        "{%0,%1,%2,%3}, {%4,%5,%6,%7}, {%8,%9}, {%0,%1,%2,%3};"
        : "+f"(d.x), "+f"(d.y), "+f"(d.z), "+f"(d.w)
        : "r"(a0), "r"(a1), "r"(a2), "r"(a3), "r"(b0), "r"(b1));
}

// ---------------------------------------------------------------------------
// K1 (mma + cp.async 2-stage): [Wq;Wk](128x512) @ x[b](512x4096) + bias, delu
// Also emits per-block Ksum partials (sum over this block's 128 n of delu(K)).
// ---------------------------------------------------------------------------
#define K1_ABUF (128 * 36)
#define K1_BBUF (32 * 136)
#define K1_SMEM ((2 * K1_ABUF + 2 * K1_BBUF) * 4)

__global__ __launch_bounds__(256) void k1_qk(
    const float* __restrict__ x,
    const float* __restrict__ wq, const float* __restrict__ bq,
    const float* __restrict__ wk, const float* __restrict__ bk)
{
    const int b  = blockIdx.y;
    const int n0 = blockIdx.x * 128;
    const int tid = threadIdx.x;
    const int wid = tid >> 5, lane = tid & 31;
    const int g = lane >> 2, tig = lane & 3;
    const int wm0 = (wid >> 1) * 32;
    const int wn0 = (wid & 1) * 64;

    extern __shared__ float dsm[];
    float* sA = dsm;
    float* sB = dsm + 2 * K1_ABUF;
    const uint32_t sA_addr = smem_u32(sA);
    const uint32_t sB_addr = smem_u32(sB);
    const uint32_t* sAu = reinterpret_cast<const uint32_t*>(sA);
    const uint32_t* sBu = reinterpret_cast<const uint32_t*>(sB);
    __shared__ float sKpart[64][2];   // [k-row][n-half]

    float4 acc[2][8];
#pragma unroll
    for (int i = 0; i < 2; i++)
#pragma unroll
        for (int j = 0; j < 8; j++) acc[i][j] = make_float4(0.f, 0.f, 0.f, 0.f);

#define K1_ISSUE(ch) do {                                                        \
    const int k0_ = (ch) * 32; const int buf_ = (ch) & 1;                        \
    _Pragma("unroll")                                                            \
    for (int i = 0; i < 4; i++) {                                                \
        int idx = tid + i * 256;                                                 \
        int r = idx >> 3; int kk = (idx & 7) << 2;                               \
        const float* src = (r < 64) ? (wq + (size_t)r * CC + k0_ + kk)           \
                                    : (wk + (size_t)(r - 64) * CC + k0_ + kk);   \
        CP16(sA_addr + (uint32_t)(buf_ * K1_ABUF + r * 36 + kk) * 4, src);       \
    }                                                                            \
    _Pragma("unroll")                                                            \
    for (int i = 0; i < 4; i++) {                                                \
        int idx = tid + i * 256;                                                 \
        int kk = idx >> 5; int j = (idx & 31) << 2;                              \
        const float* src = x + ((size_t)(b * CC + k0_ + kk)) * NN + n0 + j;      \
        CP16(sB_addr + (uint32_t)(buf_ * K1_BBUF + kk * 136 + j) * 4, src);      \
    }                                                                            \
    CP_COMMIT();                                                                 \
} while (0)

    K1_ISSUE(0);
    for (int ch = 0; ch < 16; ch++) {
        if (ch < 15) { K1_ISSUE(ch + 1); CP_WAIT1(); } else { CP_WAIT0(); }
        __syncthreads();
        const uint32_t* A = sAu + (ch & 1) * K1_ABUF;
        const uint32_t* Bm = sBu + (ch & 1) * K1_BBUF;
#pragma unroll
        for (int ks = 0; ks < 32; ks += 8) {
            uint32_t a[2][4];
#pragma unroll
            for (int i = 0; i < 2; i++) {
                int r = wm0 + i * 16 + g;
                a[i][0] = A[r * 36 + ks + tig];
                a[i][1] = A[(r + 8) * 36 + ks + tig];
                a[i][2] = A[r * 36 + ks + tig + 4];
                a[i][3] = A[(r + 8) * 36 + ks + tig + 4];
            }
#pragma unroll
            for (int j = 0; j < 8; j++) {
                int n = wn0 + j * 8 + g;
                uint32_t b0 = Bm[(ks + tig) * 136 + n];
                uint32_t b1 = Bm[(ks + tig + 4) * 136 + n];
#pragma unroll
                for (int i = 0; i < 2; i++)
                    mma_tf32(acc[i][j], a[i][0], a[i][1], a[i][2], a[i][3], b0, b1);
            }
        }
        __syncthreads();
    }

    // epilogue: bias + delu -> Qf / Kf, plus Ksum partials for K rows
    float psum[2][2] = {{0.f, 0.f}, {0.f, 0.f}};
#pragma unroll
    for (int i = 0; i < 2; i++) {
        int r0 = wm0 + i * 16 + g;
        int r1 = r0 + 8;
        float bias0 = (r0 < 64) ? bq[r0] : bk[r0 - 64];
        float bias1 = (r1 < 64) ? bq[r1] : bk[r1 - 64];
        float* dst0 = (r0 < 64) ? &g_Qf[b][r0][0] : &g_Kf[b][r0 - 64][0];
        float* dst1 = (r1 < 64) ? &g_Qf[b][r1][0] : &g_Kf[b][r1 - 64][0];
#pragma unroll
        for (int j = 0; j < 8; j++) {
            int n = n0 + wn0 + j * 8 + 2 * tig;
            float2 o0 = make_float2(delu_f(acc[i][j].x + bias0), delu_f(acc[i][j].y + bias0));
            float2 o1 = make_float2(delu_f(acc[i][j].z + bias1), delu_f(acc[i][j].w + bias1));
            *reinterpret_cast<float2*>(dst0 + n) = o0;
            *reinterpret_cast<float2*>(dst1 + n) = o1;
            psum[i][0] += o0.x + o0.y;
            psum[i][1] += o1.x + o1.y;
        }
    }
    // reduce across the 4 lanes (tig) sharing each row
#pragma unroll
    for (int i = 0; i < 2; i++)
#pragma unroll
        for (int h = 0; h < 2; h++) {
            psum[i][h] += __shfl_xor_sync(0xffffffffu, psum[i][h], 1);
            psum[i][h] += __shfl_xor_sync(0xffffffffu, psum[i][h], 2);
        }
    if (tig == 0 && wm0 >= 64) {
#pragma unroll
        for (int i = 0; i < 2; i++) {
            int r0 = wm0 + i * 16 + g;
            sKpart[r0 - 64][wid & 1] = psum[i][0];
            sKpart[r0 - 64 + 8][wid & 1] = psum[i][1];
        }
    }
    __syncthreads();
    if (tid < 64)
        g_Ksp[blockIdx.x][b][tid] = sKpart[tid][0] + sKpart[tid][1];
}

// ---------------------------------------------------------------------------
// K2 (mma + cp.async 2-stage): Mp[ns][b][c][d] = sum_n x[b][c][n]*Kf[b][d][n]
// ---------------------------------------------------------------------------
#define K2_XBUF (128 * 36)
#define K2_KBUF (64 * 36)
#define K2_SMEM ((2 * K2_XBUF + 2 * K2_KBUF) * 4)

__global__ __launch_bounds__(256) void k2_mma(const float* __restrict__ x)
{
    const int b  = blockIdx.y;
    const int c0 = blockIdx.x * 128;
    const int ns = blockIdx.z;
    const int nbase = ns * (NN / K2_NS);       // 512 per split
    const int tid = threadIdx.x;
    const int wid = tid >> 5, lane = tid & 31;
    const int g = lane >> 2, tig = lane & 3;
    const int wc0 = (wid >> 1) * 32;
    const int wd0 = (wid & 1) * 32;

    extern __shared__ float dsm[];
    float* sX = dsm;
    float* sK = dsm + 2 * K2_XBUF;
    const uint32_t sX_addr = smem_u32(sX);
    const uint32_t sK_addr = smem_u32(sK);
    const uint32_t* sXu = reinterpret_cast<const uint32_t*>(sX);
    const uint32_t* sKu = reinterpret_cast<const uint32_t*>(sK);

    float4 acc[2][4];
#pragma unroll
    for (int i = 0; i < 2; i++)
#pragma unroll
        for (int j = 0; j < 4; j++) acc[i][j] = make_float4(0.f, 0.f, 0.f, 0.f);

#define K2_ISSUE(ch) do {                                                        \
    const int nb_ = nbase + (ch) * 32; const int buf_ = (ch) & 1;                \
    _Pragma("unroll")                                                            \
    for (int i = 0; i < 4; i++) {                                                \
        int idx = tid + i * 256;                                                 \
        int r = idx >> 3; int kk = (idx & 7) << 2;                               \
        const float* src = x + ((size_t)(b * CC + c0 + r)) * NN + nb_ + kk;      \
        CP16(sX_addr + (uint32_t)(buf_ * K2_XBUF + r * 36 + kk) * 4, src);       \
    }                                                                            \
    _Pragma("unroll")                                                            \
    for (int i = 0; i < 2; i++) {                                                \
        int idx = tid + i * 256;                                                 \
        int r = idx >> 3; int kk = (idx & 7) << 2;                               \
        const float* src = &g_Kf[b][r][nb_ + kk];                                \
        CP16(sK_addr + (uint32_t)(buf_ * K2_KBUF + r * 36 + kk) * 4, src);       \
    }                                                                            \
    CP_COMMIT();                                                                 \
} while (0)

    K2_ISSUE(0);
    for (int ch = 0; ch < 16; ch++) {
        if (ch < 15) { K2_ISSUE(ch + 1); CP_WAIT1(); } else { CP_WAIT0(); }
        __syncthreads();
        const uint32_t* X = sXu + (ch & 1) * K2_XBUF;
        const uint32_t* Km = sKu + (ch & 1) * K2_KBUF;
#pragma unroll
        for (int ks = 0; ks < 32; ks += 8) {
            uint32_t a[2][4];
#pragma unroll
            for (int i = 0; i < 2; i++) {
                int r = wc0 + i * 16 + g;
                a[i][0] = X[r * 36 + ks + tig];
                a[i][1] = X[(r + 8) * 36 + ks + tig];
                a[i][2] = X[r * 36 + ks + tig + 4];
                a[i][3] = X[(r + 8) * 36 + ks + tig + 4];
            }
#pragma unroll
            for (int j = 0; j < 4; j++) {
                int d = wd0 + j * 8 + g;
                uint32_t b0 = Km[d * 36 + ks + tig];
                uint32_t b1 = Km[d * 36 + ks + tig + 4];
#pragma unroll
                for (int i = 0; i < 2; i++)
                    mma_tf32(acc[i][j], a[i][0], a[i][1], a[i][2], a[i][3], b0, b1);
            }
        }
        __syncthreads();
    }
#pragma unroll
    for (int i = 0; i < 2; i++) {
        int r0 = c0 + wc0 + i * 16 + g;
#pragma unroll
        for (int j = 0; j < 4; j++) {
            int d = wd0 + j * 8 + 2 * tig;
            *reinterpret_cast<float2*>(&g_Mp[ns][b][r0][d])     = make_float2(acc[i][j].x, acc[i][j].y);
            *reinterpret_cast<float2*>(&g_Mp[ns][b][r0 + 8][d]) = make_float2(acc[i][j].z, acc[i][j].w);
        }
    }
}

// ---------------------------------------------------------------------------
// K2b: Msum = sum_ns Mp (blocks 0..255), Ksum = sum_nb Ksp (block 256)
// ---------------------------------------------------------------------------
__global__ __launch_bounds__(256) void k2b_msum()
{
    if (blockIdx.x == 256) {
        // Ksum reduce: 512 (b,d) pairs over 32 n-tile partials; 256 thr x 2
        for (int t = threadIdx.x; t < BB * DD; t += 256) {
            const int b = t >> 6, d = t & 63;
            float s = 0.f;
#pragma unroll
            for (int nb = 0; nb < 32; nb++) s += g_Ksp[nb][b][d];
            g_Ksum[b][d] = s;
        }
        return;
    }
    const int f = blockIdx.x * 256 + threadIdx.x;   // 0..65535
    const int b = f >> 13;
    const int r = f & 8191;
    const int c = r >> 4;
    const int d4 = (r & 15) << 2;

    float4 s = make_float4(0.f, 0.f, 0.f, 0.f);
#pragma unroll
    for (int ns = 0; ns < K2_NS; ns++) {
        float4 v = *reinterpret_cast<const float4*>(&g_Mp[ns][b][c][d4]);
        s.x += v.x; s.y += v.y; s.z += v.z; s.w += v.w;
    }
    *reinterpret_cast<float4*>(&g_Msum[b][c][d4]) = s;
}

// ---------------------------------------------------------------------------
// K3 (mma): KVp[cs][b][m][e] = sum_{c in 128-split} Msum[b][c][m] * wv[e][c]
// grid (4 e-tiles, 8 b, 4 cs) = 128 blocks, 256 thr. Tile 64m x 128e, K-chunk 32.
// ---------------------------------------------------------------------------
__global__ __launch_bounds__(256) void k3_mma(const float* __restrict__ wv)
{
    const int b  = blockIdx.y;
    const int e0 = blockIdx.x * 128;
    const int cs = blockIdx.z;
    const int cb0 = cs * 128;
    const int tid = threadIdx.x;
    const int wid = tid >> 5, lane = tid & 31;
    const int g = lane >> 2, tig = lane & 3;
    const int wm0 = (wid >> 2) * 32;   // 2 m-warps
    const int we0 = (wid & 3) * 32;    // 4 e-warps

    __shared__ float sM[32 * 72];      // [c][m] stride 72
    __shared__ float sW[128 * 36];     // [e][c] stride 36
    const uint32_t* sMu = reinterpret_cast<const uint32_t*>(sM);
    const uint32_t* sWu = reinterpret_cast<const uint32_t*>(sW);

    float4 acc[2][4];
#pragma unroll
    for (int i = 0; i < 2; i++)
#pragma unroll
        for (int j = 0; j < 4; j++) acc[i][j] = make_float4(0.f, 0.f, 0.f, 0.f);

    for (int cc = 0; cc < 128; cc += 32) {
        const int ca = cb0 + cc;
        // Msum tile: 32 c x 64 m = 512 float4
#pragma unroll
        for (int i = 0; i < 2; i++) {
            int idx = tid + i * 256;
            int c = idx >> 4;
            int m = (idx & 15) << 2;
            float4 v = *reinterpret_cast<const float4*>(&g_Msum[b][ca + c][m]);
            *reinterpret_cast<float4*>(&sM[c * 72 + m]) = v;
        }
        // wv tile: 128 e x 32 c = 1024 float4
#pragma unroll
        for (int i = 0; i < 4; i++) {
            int idx = tid + i * 256;
            int e = idx >> 3;
            int k = (idx & 7) << 2;
            float4 v = *reinterpret_cast<const float4*>(
                wv + (size_t)(e0 + e) * CC + ca + k);
            *reinterpret_cast<float4*>(&sW[e * 36 + k]) = v;
        }
        __syncthreads();
#pragma unroll
        for (int ks = 0; ks < 32; ks += 8) {
            uint32_t a[2][4];
#pragma unroll
            for (int i = 0; i < 2; i++) {
                int r = wm0 + i * 16 + g;
                a[i][0] = sMu[(ks + tig) * 72 + r];
                a[i][1] = sMu[(ks + tig) * 72 + r + 8];
                a[i][2] = sMu[(ks + tig + 4) * 72 + r];
                a[i][3] = sMu[(ks + tig + 4) * 72 + r + 8];
            }
#pragma unroll
            for (int j = 0; j < 4; j++) {
                int e = we0 + j * 8 + g;
                uint32_t b0 = sWu[e * 36 + ks + tig];
                uint32_t b1 = sWu[e * 36 + ks + tig + 4];
#pragma unroll
                for (int i = 0; i < 2; i++)
                    mma_tf32(acc[i][j], a[i][0], a[i][1], a[i][2], a[i][3], b0, b1);
            }
        }
        __syncthreads();
    }
#pragma unroll
    for (int i = 0; i < 2; i++) {
        int m0 = wm0 + i * 16 + g;
#pragma unroll
        for (int j = 0; j < 4; j++) {
            int e = e0 + we0 + j * 8 + 2 * tig;
            *reinterpret_cast<float2*>(&g_KVp[cs][b][m0][e])     = make_float2(acc[i][j].x, acc[i][j].y);
            *reinterpret_cast<float2*>(&g_KVp[cs][b][m0 + 8][e]) = make_float2(acc[i][j].z, acc[i][j].w);
        }
    }
}

// ---------------------------------------------------------------------------
// K3c: KV = sum_cs KVp + Ksum (x) bv.  64K float4; grid 256 x 256
// ---------------------------------------------------------------------------
__global__ __launch_bounds__(256) void k3c_merge(const float* __restrict__ bv)
{
    const int f = blockIdx.x * 256 + threadIdx.x;
    const int b = f >> 13;
    const int r = f & 8191;
    const int m = r >> 7;
    const int e4 = (r & 127) << 2;

    float4 s0 = *reinterpret_cast<const float4*>(&g_KVp[0][b][m][e4]);
    float4 s1 = *reinterpret_cast<const float4*>(&g_KVp[1][b][m][e4]);
    float4 s2 = *reinterpret_cast<const float4*>(&g_KVp[2][b][m][e4]);
    float4 s3 = *reinterpret_cast<const float4*>(&g_KVp[3][b][m][e4]);
    float4 bb = *reinterpret_cast<const float4*>(bv + e4);
    const float ks = g_Ksum[b][m];
    float4 o;
    o.x = s0.x + s1.x + s2.x + s3.x + ks * bb.x;
    o.y = s0.y + s1.y + s2.y + s3.y + ks * bb.y;
    o.z = s0.z + s1.z + s2.z + s3.z + ks * bb.z;
    o.w = s0.w + s1.w + s2.w + s3.w + ks * bb.w;
    *reinterpret_cast<float4*>(&g_KV[b][m][e4]) = o;
}

// ---------------------------------------------------------------------------
// K4 (mma + cp.async prefetch): out = x + gamma * norm[n] * (Qf^T @ KV)^T
// grid (4 c-tiles, 32 n-tiles, 8 b) — c fastest for Qf L2 reuse.
// dyn smem: sQ[64][136] + sV[64][136] + sX[128][128]
// ---------------------------------------------------------------------------
#define K4_QV (64 * 136)
#define K4_SMEM ((2 * K4_QV + 128 * 128) * 4)

__global__ __launch_bounds__(256) void k4_out(
    const float* __restrict__ x, const float* __restrict__ gamma,
    float* __restrict__ out)
{
    const int b  = blockIdx.z;
    const int c0 = blockIdx.x * 128;
    const int n0 = blockIdx.y * 128;
    const int tid = threadIdx.x;
    const int wid = tid >> 5, lane = tid & 31;
    const int g = lane >> 2, tig = lane & 3;
    const int wc0 = (wid >> 1) * 32;
    const int wn0 = (wid & 1) * 64;

    extern __shared__ float smem[];
    float* sQ = smem;                  // [d][n] stride 136
    float* sV = smem + K4_QV;          // [d][c] stride 136
    float* sX = smem + 2 * K4_QV;      // [c][n] 128x128
    const uint32_t sQ_addr = smem_u32(sQ);
    const uint32_t sV_addr = smem_u32(sV);
    const uint32_t sX_addr = smem_u32(sX);
    const uint32_t* sQu = reinterpret_cast<const uint32_t*>(sQ);
    const uint32_t* sVu = reinterpret_cast<const uint32_t*>(sV);
    __shared__ float snorm[128];
    __shared__ float sKs[64];

    // group 0: Qf + KV tiles
#pragma unroll
    for (int i = 0; i < 8; i++) {
        int idx = tid + i * 256;
        int d = idx >> 5;
        int j = (idx & 31) << 2;
        CP16(sQ_addr + (uint32_t)(d * 136 + j) * 4, &g_Qf[b][d][n0 + j]);
    }
#pragma unroll
    for (int i = 0; i < 8; i++) {
        int idx = tid + i * 256;
        int d = idx >> 5;
        int j = (idx & 31) << 2;
        CP16(sV_addr + (uint32_t)(d * 136 + j) * 4, &g_KV[b][d][c0 + j]);
    }
    CP_COMMIT();
    // group 1: x tile (consumed only in epilogue)
#pragma unroll
    for (int i = 0; i < 16; i++) {
        int idx = tid + i * 256;
        int c = idx >> 5;
        int j = (idx & 31) << 2;
        CP16(sX_addr + (uint32_t)(c * 128 + j) * 4,
             x + ((size_t)(b * CC + c0 + c)) * NN + n0 + j);
    }
    CP_COMMIT();

    if (tid < 64) sKs[tid] = g_Ksum[b][tid] + 1e-10f;
    CP_WAIT1();            // Qf + KV ready; x still in flight
    __syncthreads();

    if (tid < 128) {
        float s = 0.f;
#pragma unroll
        for (int d = 0; d < 64; d++) s += sQ[d * 136 + tid] * sKs[d];
        snorm[tid] = 1.0f / s;
    }
    __syncthreads();

    float4 acc[2][8];
#pragma unroll
    for (int i = 0; i < 2; i++)
#pragma unroll
        for (int j = 0; j < 8; j++) acc[i][j] = make_float4(0.f, 0.f, 0.f, 0.f);

#pragma unroll
    for (int ks = 0; ks < 64; ks += 8) {
        uint32_t a[2][4];
#pragma unroll
        for (int i = 0; i < 2; i++) {
            int r = wc0 + i * 16 + g;
            a[i][0] = sVu[(ks + tig) * 136 + r];
            a[i][1] = sVu[(ks + tig) * 136 + r + 8];
            a[i][2] = sVu[(ks + tig + 4) * 136 + r];
            a[i][3] = sVu[(ks + tig + 4) * 136 + r + 8];
        }
#pragma unroll
        for (int j = 0; j < 8; j++) {
            int n = wn0 + j * 8 + g;
            uint32_t b0 = sQu[(ks + tig) * 136 + n];
            uint32_t b1 = sQu[(ks + tig + 4) * 136 + n];
#pragma unroll
            for (int i = 0; i < 2; i++)
                mma_tf32(acc[i][j], a[i][0], a[i][1], a[i][2], a[i][3], b0, b1);
        }
    }

    CP_WAIT0();
    __syncthreads();

    const float gm = gamma[0];
#pragma unroll
    for (int i = 0; i < 2; i++) {
        int cl0 = wc0 + i * 16 + g;
        int cl1 = cl0 + 8;
#pragma unroll
        for (int j = 0; j < 8; j++) {
            int nl = wn0 + j * 8 + 2 * tig;
            float nm0 = snorm[nl], nm1 = snorm[nl + 1];
            float2 x0 = *reinterpret_cast<const float2*>(&sX[cl0 * 128 + nl]);
            float2 x1 = *reinterpret_cast<const float2*>(&sX[cl1 * 128 + nl]);
            size_t off0 = ((size_t)b * CC + c0 + cl0) * NN + n0 + nl;
            size_t off1 = ((size_t)b * CC + c0 + cl1) * NN + n0 + nl;
            float2 o0 = make_float2(x0.x + gm * acc[i][j].x * nm0,
                                    x0.y + gm * acc[i][j].y * nm1);
            float2 o1 = make_float2(x1.x + gm * acc[i][j].z * nm0,
                                    x1.y + gm * acc[i][j].w * nm1);
            *reinterpret_cast<float2*>(out + off0) = o0;
            *reinterpret_cast<float2*>(out + off1) = o1;
        }
    }
}

// ---------------------------------------------------------------------------
extern "C" void kernel_launch(void* const* d_in, const int* in_sizes, int n_in,
                              void* d_out, int out_size)
{
    const float* x     = (const float*)d_in[0];
    const float* wq    = (const float*)d_in[1];
    const float* bq    = (const float*)d_in[2];
    const float* wk    = (const float*)d_in[3];
    const float* bk    = (const float*)d_in[4];
    const float* wv    = (const float*)d_in[5];
    const float* bv    = (const float*)d_in[6];
    const float* gamma = (const float*)d_in[7];
    float* out = (float*)d_out;

    static bool attr_set = false;
    if (!attr_set) {
        cudaFuncSetAttribute(k1_qk,  cudaFuncAttributeMaxDynamicSharedMemorySize, K1_SMEM);
        cudaFuncSetAttribute(k2_mma, cudaFuncAttributeMaxDynamicSharedMemorySize, K2_SMEM);
        cudaFuncSetAttribute(k4_out, cudaFuncAttributeMaxDynamicSharedMemorySize, K4_SMEM);
        attr_set = true;
    }

    k1_qk<<<dim3(NN / 128, BB), 256, K1_SMEM>>>(x, wq, bq, wk, bk);
    k2_mma<<<dim3(CC / 128, BB, K2_NS), 256, K2_SMEM>>>(x);
    k2b_msum<<<257, 256>>>();
    k3_mma<<<dim3(CC / 128, BB, 4), 256>>>(wv);
    k3c_merge<<<256, 256>>>(bv);
    k4_out<<<dim3(CC / 128, NN / 128, BB), 256, K4_SMEM>>>(x, gamma, out);
}

// round 7
// speedup vs baseline: 1.0678x; 1.0170x over previous
#include <cuda_runtime.h>
#include <cuda_bf16.h>
#include <cstdint>

// Problem constants (fixed by the dataset)
#define BB 8
#define CC 512
#define NN 4096
#define DD 64
#define K2_NS 8   // n-splits for k2
#define K3_CS 8   // c-splits for k3

// Scratch (static device globals — no allocation)
__device__ float g_Qf[BB][DD][NN];          // delu(Q)  8 MB
__device__ float g_Kf[BB][DD][NN];          // delu(K)  8 MB
__device__ float g_Mp[K2_NS][BB][CC][DD];   // partial M^T: [ns][b][c][d]
__device__ float g_Msum[BB][CC][DD];        // summed M^T (1 MB)
__device__ float g_KVp[K3_CS][BB][DD][CC];  // partial KV (c-splits)
__device__ float g_KV[BB][DD][CC];          // KV = M @ wv^T + Ksum (x) bv
__device__ float g_Ksp[32][BB][DD];         // per-n-tile Ksum partials (from k1)
__device__ float g_Ksum[BB][DD];

__device__ __forceinline__ float delu_f(float v) {
    return 10.0f * fmaxf(v, 0.0f) + __expf(10.0f * fminf(v, 0.0f));
}

__device__ __forceinline__ uint32_t smem_u32(const void* p) {
    uint32_t a;
    asm("{ .reg .u64 t; cvta.to.shared.u64 t, %1; cvt.u32.u64 %0, t; }"
        : "=r"(a) : "l"(p));
    return a;
}

#define CP16(dst, src) \
    asm volatile("cp.async.cg.shared.global [%0], [%1], 16;" :: "r"(dst), "l"(src))
#define CP_COMMIT() asm volatile("cp.async.commit_group;" ::: "memory")
#define CP_WAIT1()  asm volatile("cp.async.wait_group 1;" ::: "memory")
#define CP_WAIT0()  asm volatile("cp.async.wait_group 0;" ::: "memory")

// D += A(16x8) * B(8x8), tf32 inputs (fp32 bits, HW-truncated), f32 accum
__device__ __forceinline__ void mma_tf32(float4& d,
                                         uint32_t a0, uint32_t a1, uint32_t a2, uint32_t a3,
                                         uint32_t b0, uint32_t b1) {
    asm volatile(
        "mma.sync.aligned.m16n8k8.row.col.f32.tf32.tf32.f32 "
        "{%0,%1,%2,%3}, {%4,%5,%6,%7}, {%8,%9}, {%0,%1,%2,%3};"
        : "+f"(d.x), "+f"(d.y), "+f"(d.z), "+f"(d.w)
        : "r"(a0), "r"(a1), "r"(a2), "r"(a3), "r"(b0), "r"(b1));
}

// ---------------------------------------------------------------------------
// K1 (mma + cp.async 2-stage): [Wq;Wk](128x512) @ x[b](512x4096) + bias, delu
// Also emits per-block Ksum partials.
// ---------------------------------------------------------------------------
#define K1_ABUF (128 * 36)
#define K1_BBUF (32 * 136)
#define K1_SMEM ((2 * K1_ABUF + 2 * K1_BBUF) * 4)

__global__ __launch_bounds__(256) void k1_qk(
    const float* __restrict__ x,
    const float* __restrict__ wq, const float* __restrict__ bq,
    const float* __restrict__ wk, const float* __restrict__ bk)
{
    const int b  = blockIdx.y;
    const int n0 = blockIdx.x * 128;
    const int tid = threadIdx.x;
    const int wid = tid >> 5, lane = tid & 31;
    const int g = lane >> 2, tig = lane & 3;
    const int wm0 = (wid >> 1) * 32;
    const int wn0 = (wid & 1) * 64;

    extern __shared__ float dsm[];
    float* sA = dsm;
    float* sB = dsm + 2 * K1_ABUF;
    const uint32_t sA_addr = smem_u32(sA);
    const uint32_t sB_addr = smem_u32(sB);
    const uint32_t* sAu = reinterpret_cast<const uint32_t*>(sA);
    const uint32_t* sBu = reinterpret_cast<const uint32_t*>(sB);
    __shared__ float sKpart[64][2];   // [k-row][n-half]

    float4 acc[2][8];
#pragma unroll
    for (int i = 0; i < 2; i++)
#pragma unroll
        for (int j = 0; j < 8; j++) acc[i][j] = make_float4(0.f, 0.f, 0.f, 0.f);

#define K1_ISSUE(ch) do {                                                        \
    const int k0_ = (ch) * 32; const int buf_ = (ch) & 1;                        \
    _Pragma("unroll")                                                            \
    for (int i = 0; i < 4; i++) {                                                \
        int idx = tid + i * 256;                                                 \
        int r = idx >> 3; int kk = (idx & 7) << 2;                               \
        const float* src = (r < 64) ? (wq + (size_t)r * CC + k0_ + kk)           \
                                    : (wk + (size_t)(r - 64) * CC + k0_ + kk);   \
        CP16(sA_addr + (uint32_t)(buf_ * K1_ABUF + r * 36 + kk) * 4, src);       \
    }                                                                            \
    _Pragma("unroll")                                                            \
    for (int i = 0; i < 4; i++) {                                                \
        int idx = tid + i * 256;                                                 \
        int kk = idx >> 5; int j = (idx & 31) << 2;                              \
        const float* src = x + ((size_t)(b * CC + k0_ + kk)) * NN + n0 + j;      \
        CP16(sB_addr + (uint32_t)(buf_ * K1_BBUF + kk * 136 + j) * 4, src);      \
    }                                                                            \
    CP_COMMIT();                                                                 \
} while (0)

    K1_ISSUE(0);
    for (int ch = 0; ch < 16; ch++) {
        if (ch < 15) { K1_ISSUE(ch + 1); CP_WAIT1(); } else { CP_WAIT0(); }
        __syncthreads();
        const uint32_t* A = sAu + (ch & 1) * K1_ABUF;
        const uint32_t* Bm = sBu + (ch & 1) * K1_BBUF;
#pragma unroll
        for (int ks = 0; ks < 32; ks += 8) {
            uint32_t a[2][4];
#pragma unroll
            for (int i = 0; i < 2; i++) {
                int r = wm0 + i * 16 + g;
                a[i][0] = A[r * 36 + ks + tig];
                a[i][1] = A[(r + 8) * 36 + ks + tig];
                a[i][2] = A[r * 36 + ks + tig + 4];
                a[i][3] = A[(r + 8) * 36 + ks + tig + 4];
            }
#pragma unroll
            for (int j = 0; j < 8; j++) {
                int n = wn0 + j * 8 + g;
                uint32_t b0 = Bm[(ks + tig) * 136 + n];
                uint32_t b1 = Bm[(ks + tig + 4) * 136 + n];
#pragma unroll
                for (int i = 0; i < 2; i++)
                    mma_tf32(acc[i][j], a[i][0], a[i][1], a[i][2], a[i][3], b0, b1);
            }
        }
        __syncthreads();
    }

    // epilogue: bias + delu -> Qf / Kf, plus Ksum partials for K rows
    float psum[2][2] = {{0.f, 0.f}, {0.f, 0.f}};
#pragma unroll
    for (int i = 0; i < 2; i++) {
        int r0 = wm0 + i * 16 + g;
        int r1 = r0 + 8;
        float bias0 = (r0 < 64) ? bq[r0] : bk[r0 - 64];
        float bias1 = (r1 < 64) ? bq[r1] : bk[r1 - 64];
        float* dst0 = (r0 < 64) ? &g_Qf[b][r0][0] : &g_Kf[b][r0 - 64][0];
        float* dst1 = (r1 < 64) ? &g_Qf[b][r1][0] : &g_Kf[b][r1 - 64][0];
#pragma unroll
        for (int j = 0; j < 8; j++) {
            int n = n0 + wn0 + j * 8 + 2 * tig;
            float2 o0 = make_float2(delu_f(acc[i][j].x + bias0), delu_f(acc[i][j].y + bias0));
            float2 o1 = make_float2(delu_f(acc[i][j].z + bias1), delu_f(acc[i][j].w + bias1));
            *reinterpret_cast<float2*>(dst0 + n) = o0;
            *reinterpret_cast<float2*>(dst1 + n) = o1;
            psum[i][0] += o0.x + o0.y;
            psum[i][1] += o1.x + o1.y;
        }
    }
#pragma unroll
    for (int i = 0; i < 2; i++)
#pragma unroll
        for (int h = 0; h < 2; h++) {
            psum[i][h] += __shfl_xor_sync(0xffffffffu, psum[i][h], 1);
            psum[i][h] += __shfl_xor_sync(0xffffffffu, psum[i][h], 2);
        }
    if (tig == 0 && wm0 >= 64) {
#pragma unroll
        for (int i = 0; i < 2; i++) {
            int r0 = wm0 + i * 16 + g;
            sKpart[r0 - 64][wid & 1] = psum[i][0];
            sKpart[r0 - 64 + 8][wid & 1] = psum[i][1];
        }
    }
    __syncthreads();
    if (tid < 64)
        g_Ksp[blockIdx.x][b][tid] = sKpart[tid][0] + sKpart[tid][1];
}

// ---------------------------------------------------------------------------
// K2 (mma + cp.async 2-stage): Mp[ns][b][c][d] = sum_n x[b][c][n]*Kf[b][d][n]
// ---------------------------------------------------------------------------
#define K2_XBUF (128 * 36)
#define K2_KBUF (64 * 36)
#define K2_SMEM ((2 * K2_XBUF + 2 * K2_KBUF) * 4)

__global__ __launch_bounds__(256) void k2_mma(const float* __restrict__ x)
{
    const int b  = blockIdx.y;
    const int c0 = blockIdx.x * 128;
    const int ns = blockIdx.z;
    const int nbase = ns * (NN / K2_NS);       // 512 per split
    const int tid = threadIdx.x;
    const int wid = tid >> 5, lane = tid & 31;
    const int g = lane >> 2, tig = lane & 3;
    const int wc0 = (wid >> 1) * 32;
    const int wd0 = (wid & 1) * 32;

    extern __shared__ float dsm[];
    float* sX = dsm;
    float* sK = dsm + 2 * K2_XBUF;
    const uint32_t sX_addr = smem_u32(sX);
    const uint32_t sK_addr = smem_u32(sK);
    const uint32_t* sXu = reinterpret_cast<const uint32_t*>(sX);
    const uint32_t* sKu = reinterpret_cast<const uint32_t*>(sK);

    float4 acc[2][4];
#pragma unroll
    for (int i = 0; i < 2; i++)
#pragma unroll
        for (int j = 0; j < 4; j++) acc[i][j] = make_float4(0.f, 0.f, 0.f, 0.f);

#define K2_ISSUE(ch) do {                                                        \
    const int nb_ = nbase + (ch) * 32; const int buf_ = (ch) & 1;                \
    _Pragma("unroll")                                                            \
    for (int i = 0; i < 4; i++) {                                                \
        int idx = tid + i * 256;                                                 \
        int r = idx >> 3; int kk = (idx & 7) << 2;                               \
        const float* src = x + ((size_t)(b * CC + c0 + r)) * NN + nb_ + kk;      \
        CP16(sX_addr + (uint32_t)(buf_ * K2_XBUF + r * 36 + kk) * 4, src);       \
    }                                                                            \
    _Pragma("unroll")                                                            \
    for (int i = 0; i < 2; i++) {                                                \
        int idx = tid + i * 256;                                                 \
        int r = idx >> 3; int kk = (idx & 7) << 2;                               \
        const float* src = &g_Kf[b][r][nb_ + kk];                                \
        CP16(sK_addr + (uint32_t)(buf_ * K2_KBUF + r * 36 + kk) * 4, src);       \
    }                                                                            \
    CP_COMMIT();                                                                 \
} while (0)

    K2_ISSUE(0);
    for (int ch = 0; ch < 16; ch++) {
        if (ch < 15) { K2_ISSUE(ch + 1); CP_WAIT1(); } else { CP_WAIT0(); }
        __syncthreads();
        const uint32_t* X = sXu + (ch & 1) * K2_XBUF;
        const uint32_t* Km = sKu + (ch & 1) * K2_KBUF;
#pragma unroll
        for (int ks = 0; ks < 32; ks += 8) {
            uint32_t a[2][4];
#pragma unroll
            for (int i = 0; i < 2; i++) {
                int r = wc0 + i * 16 + g;
                a[i][0] = X[r * 36 + ks + tig];
                a[i][1] = X[(r + 8) * 36 + ks + tig];
                a[i][2] = X[r * 36 + ks + tig + 4];
                a[i][3] = X[(r + 8) * 36 + ks + tig + 4];
            }
#pragma unroll
            for (int j = 0; j < 4; j++) {
                int d = wd0 + j * 8 + g;
                uint32_t b0 = Km[d * 36 + ks + tig];
                uint32_t b1 = Km[d * 36 + ks + tig + 4];
#pragma unroll
                for (int i = 0; i < 2; i++)
                    mma_tf32(acc[i][j], a[i][0], a[i][1], a[i][2], a[i][3], b0, b1);
            }
        }
        __syncthreads();
    }
#pragma unroll
    for (int i = 0; i < 2; i++) {
        int r0 = c0 + wc0 + i * 16 + g;
#pragma unroll
        for (int j = 0; j < 4; j++) {
            int d = wd0 + j * 8 + 2 * tig;
            *reinterpret_cast<float2*>(&g_Mp[ns][b][r0][d])     = make_float2(acc[i][j].x, acc[i][j].y);
            *reinterpret_cast<float2*>(&g_Mp[ns][b][r0 + 8][d]) = make_float2(acc[i][j].z, acc[i][j].w);
        }
    }
}

// ---------------------------------------------------------------------------
// K2b: Msum = sum_ns Mp (blocks 0..127, 2 float4/thread), Ksum (block 128)
// ---------------------------------------------------------------------------
__global__ __launch_bounds__(256) void k2b_msum()
{
    if (blockIdx.x == 128) {
        for (int t = threadIdx.x; t < BB * DD; t += 256) {
            const int b = t >> 6, d = t & 63;
            float s = 0.f;
#pragma unroll
            for (int nb = 0; nb < 32; nb++) s += g_Ksp[nb][b][d];
            g_Ksum[b][d] = s;
        }
        return;
    }
    const float4* src = reinterpret_cast<const float4*>(g_Mp);
    float4* dst = reinterpret_cast<float4*>(g_Msum);
    const int f0 = blockIdx.x * 256 + threadIdx.x;   // two elements: f0, f0+32768
#pragma unroll
    for (int h = 0; h < 2; h++) {
        const int f = f0 + h * 32768;                // 0..65535 over b*c*d/4
        float4 s = make_float4(0.f, 0.f, 0.f, 0.f);
#pragma unroll
        for (int ns = 0; ns < K2_NS; ns++) {
            float4 v = src[(size_t)ns * 65536 + f];
            s.x += v.x; s.y += v.y; s.z += v.z; s.w += v.w;
        }
        dst[f] = s;
    }
}

// ---------------------------------------------------------------------------
// K3 (mma): KVp[cs][b][m][e] = sum_{c in 64-split} Msum[b][c][m] * wv[e][c]
// grid (4 e-tiles, 8 b, 8 cs) = 256 blocks, 256 thr. Tile 64m x 128e, K=64.
// ---------------------------------------------------------------------------
__global__ __launch_bounds__(256) void k3_mma(const float* __restrict__ wv)
{
    const int b  = blockIdx.y;
    const int e0 = blockIdx.x * 128;
    const int cs = blockIdx.z;
    const int cb0 = cs * 64;
    const int tid = threadIdx.x;
    const int wid = tid >> 5, lane = tid & 31;
    const int g = lane >> 2, tig = lane & 3;
    const int wm0 = (wid >> 2) * 32;   // 2 m-warps
    const int we0 = (wid & 3) * 32;    // 4 e-warps

    __shared__ float sM[32 * 72];      // [c][m] stride 72
    __shared__ float sW[128 * 36];     // [e][c] stride 36
    const uint32_t* sMu = reinterpret_cast<const uint32_t*>(sM);
    const uint32_t* sWu = reinterpret_cast<const uint32_t*>(sW);

    float4 acc[2][4];
#pragma unroll
    for (int i = 0; i < 2; i++)
#pragma unroll
        for (int j = 0; j < 4; j++) acc[i][j] = make_float4(0.f, 0.f, 0.f, 0.f);

#pragma unroll
    for (int cc = 0; cc < 64; cc += 32) {
        const int ca = cb0 + cc;
        // Msum tile: 32 c x 64 m = 512 float4
#pragma unroll
        for (int i = 0; i < 2; i++) {
            int idx = tid + i * 256;
            int c = idx >> 4;
            int m = (idx & 15) << 2;
            float4 v = *reinterpret_cast<const float4*>(&g_Msum[b][ca + c][m]);
            *reinterpret_cast<float4*>(&sM[c * 72 + m]) = v;
        }
        // wv tile: 128 e x 32 c = 1024 float4
#pragma unroll
        for (int i = 0; i < 4; i++) {
            int idx = tid + i * 256;
            int e = idx >> 3;
            int k = (idx & 7) << 2;
            float4 v = *reinterpret_cast<const float4*>(
                wv + (size_t)(e0 + e) * CC + ca + k);
            *reinterpret_cast<float4*>(&sW[e * 36 + k]) = v;
        }
        __syncthreads();
#pragma unroll
        for (int ks = 0; ks < 32; ks += 8) {
            uint32_t a[2][4];
#pragma unroll
            for (int i = 0; i < 2; i++) {
                int r = wm0 + i * 16 + g;
                a[i][0] = sMu[(ks + tig) * 72 + r];
                a[i][1] = sMu[(ks + tig) * 72 + r + 8];
                a[i][2] = sMu[(ks + tig + 4) * 72 + r];
                a[i][3] = sMu[(ks + tig + 4) * 72 + r + 8];
            }
#pragma unroll
            for (int j = 0; j < 4; j++) {
                int e = we0 + j * 8 + g;
                uint32_t b0 = sWu[e * 36 + ks + tig];
                uint32_t b1 = sWu[e * 36 + ks + tig + 4];
#pragma unroll
                for (int i = 0; i < 2; i++)
                    mma_tf32(acc[i][j], a[i][0], a[i][1], a[i][2], a[i][3], b0, b1);
            }
        }
        __syncthreads();
    }
#pragma unroll
    for (int i = 0; i < 2; i++) {
        int m0 = wm0 + i * 16 + g;
#pragma unroll
        for (int j = 0; j < 4; j++) {
            int e = e0 + we0 + j * 8 + 2 * tig;
            *reinterpret_cast<float2*>(&g_KVp[cs][b][m0][e])     = make_float2(acc[i][j].x, acc[i][j].y);
            *reinterpret_cast<float2*>(&g_KVp[cs][b][m0 + 8][e]) = make_float2(acc[i][j].z, acc[i][j].w);
        }
    }
}

// ---------------------------------------------------------------------------
// K3c: KV = sum_cs KVp + Ksum (x) bv.  64K float4; grid 256 x 256
// ---------------------------------------------------------------------------
__global__ __launch_bounds__(256) void k3c_merge(const float* __restrict__ bv)
{
    const int f = blockIdx.x * 256 + threadIdx.x;
    const int b = f >> 13;
    const int r = f & 8191;
    const int m = r >> 7;
    const int e4 = (r & 127) << 2;

    float4 s = make_float4(0.f, 0.f, 0.f, 0.f);
#pragma unroll
    for (int cs = 0; cs < K3_CS; cs++) {
        float4 v = *reinterpret_cast<const float4*>(&g_KVp[cs][b][m][e4]);
        s.x += v.x; s.y += v.y; s.z += v.z; s.w += v.w;
    }
    float4 bb = *reinterpret_cast<const float4*>(bv + e4);
    const float ks = g_Ksum[b][m];
    float4 o;
    o.x = s.x + ks * bb.x;
    o.y = s.y + ks * bb.y;
    o.z = s.z + ks * bb.z;
    o.w = s.w + ks * bb.w;
    *reinterpret_cast<float4*>(&g_KV[b][m][e4]) = o;
}

// ---------------------------------------------------------------------------
// K4 (mma + cp.async prefetch): out = x + gamma * norm[n] * (Qf^T @ KV)^T
// grid (4 c-tiles, 32 n-tiles, 8 b) — c fastest for Qf L2 reuse.
// ---------------------------------------------------------------------------
#define K4_QV (64 * 136)
#define K4_SMEM ((2 * K4_QV + 128 * 128) * 4)

__global__ __launch_bounds__(256) void k4_out(
    const float* __restrict__ x, const float* __restrict__ gamma,
    float* __restrict__ out)
{
    const int b  = blockIdx.z;
    const int c0 = blockIdx.x * 128;
    const int n0 = blockIdx.y * 128;
    const int tid = threadIdx.x;
    const int wid = tid >> 5, lane = tid & 31;
    const int g = lane >> 2, tig = lane & 3;
    const int wc0 = (wid >> 1) * 32;
    const int wn0 = (wid & 1) * 64;

    extern __shared__ float smem[];
    float* sQ = smem;                  // [d][n] stride 136
    float* sV = smem + K4_QV;          // [d][c] stride 136
    float* sX = smem + 2 * K4_QV;      // [c][n] 128x128
    const uint32_t sQ_addr = smem_u32(sQ);
    const uint32_t sV_addr = smem_u32(sV);
    const uint32_t sX_addr = smem_u32(sX);
    const uint32_t* sQu = reinterpret_cast<const uint32_t*>(sQ);
    const uint32_t* sVu = reinterpret_cast<const uint32_t*>(sV);
    __shared__ float snorm[128];
    __shared__ float sKs[64];

    // group 0: Qf + KV tiles
#pragma unroll
    for (int i = 0; i < 8; i++) {
        int idx = tid + i * 256;
        int d = idx >> 5;
        int j = (idx & 31) << 2;
        CP16(sQ_addr + (uint32_t)(d * 136 + j) * 4, &g_Qf[b][d][n0 + j]);
    }
#pragma unroll
    for (int i = 0; i < 8; i++) {
        int idx = tid + i * 256;
        int d = idx >> 5;
        int j = (idx & 31) << 2;
        CP16(sV_addr + (uint32_t)(d * 136 + j) * 4, &g_KV[b][d][c0 + j]);
    }
    CP_COMMIT();
    // group 1: x tile (consumed only in epilogue)
#pragma unroll
    for (int i = 0; i < 16; i++) {
        int idx = tid + i * 256;
        int c = idx >> 5;
        int j = (idx & 31) << 2;
        CP16(sX_addr + (uint32_t)(c * 128 + j) * 4,
             x + ((size_t)(b * CC + c0 + c)) * NN + n0 + j);
    }
    CP_COMMIT();

    if (tid < 64) sKs[tid] = g_Ksum[b][tid] + 1e-10f;
    CP_WAIT1();            // Qf + KV ready; x still in flight
    __syncthreads();

    // norm: 2 threads per n (d-halves), combined via shfl
    {
        int n = tid >> 1, h = tid & 1;
        float s = 0.f;
#pragma unroll
        for (int d = 0; d < 32; d++) s += sQ[(h * 32 + d) * 136 + n] * sKs[h * 32 + d];
        s += __shfl_xor_sync(0xffffffffu, s, 1);
        if (h == 0) snorm[n] = 1.0f / s;
    }
    __syncthreads();

    float4 acc[2][8];
#pragma unroll
    for (int i = 0; i < 2; i++)
#pragma unroll
        for (int j = 0; j < 8; j++) acc[i][j] = make_float4(0.f, 0.f, 0.f, 0.f);

#pragma unroll
    for (int ks = 0; ks < 64; ks += 8) {
        uint32_t a[2][4];
#pragma unroll
        for (int i = 0; i < 2; i++) {
            int r = wc0 + i * 16 + g;
            a[i][0] = sVu[(ks + tig) * 136 + r];
            a[i][1] = sVu[(ks + tig) * 136 + r + 8];
            a[i][2] = sVu[(ks + tig + 4) * 136 + r];
            a[i][3] = sVu[(ks + tig + 4) * 136 + r + 8];
        }
#pragma unroll
        for (int j = 0; j < 8; j++) {
            int n = wn0 + j * 8 + g;
            uint32_t b0 = sQu[(ks + tig) * 136 + n];
            uint32_t b1 = sQu[(ks + tig + 4) * 136 + n];
#pragma unroll
            for (int i = 0; i < 2; i++)
                mma_tf32(acc[i][j], a[i][0], a[i][1], a[i][2], a[i][3], b0, b1);
        }
    }

    CP_WAIT0();
    __syncthreads();

    const float gm = gamma[0];
#pragma unroll
    for (int i = 0; i < 2; i++) {
        int cl0 = wc0 + i * 16 + g;
        int cl1 = cl0 + 8;
#pragma unroll
        for (int j = 0; j < 8; j++) {
            int nl = wn0 + j * 8 + 2 * tig;
            float nm0 = snorm[nl], nm1 = snorm[nl + 1];
            float2 x0 = *reinterpret_cast<const float2*>(&sX[cl0 * 128 + nl]);
            float2 x1 = *reinterpret_cast<const float2*>(&sX[cl1 * 128 + nl]);
            size_t off0 = ((size_t)b * CC + c0 + cl0) * NN + n0 + nl;
            size_t off1 = ((size_t)b * CC + c0 + cl1) * NN + n0 + nl;
            float2 o0 = make_float2(x0.x + gm * acc[i][j].x * nm0,
                                    x0.y + gm * acc[i][j].y * nm1);
            float2 o1 = make_float2(x1.x + gm * acc[i][j].z * nm0,
                                    x1.y + gm * acc[i][j].w * nm1);
            *reinterpret_cast<float2*>(out + off0) = o0;
            *reinterpret_cast<float2*>(out + off1) = o1;
        }
    }
}

// ---------------------------------------------------------------------------
extern "C" void kernel_launch(void* const* d_in, const int* in_sizes, int n_in,
                              void* d_out, int out_size)
{
    const float* x     = (const float*)d_in[0];
    const float* wq    = (const float*)d_in[1];
    const float* bq    = (const float*)d_in[2];
    const float* wk    = (const float*)d_in[3];
    const float* bk    = (const float*)d_in[4];
    const float* wv    = (const float*)d_in[5];
    const float* bv    = (const float*)d_in[6];
    const float* gamma = (const float*)d_in[7];
    float* out = (float*)d_out;

    static bool attr_set = false;
    if (!attr_set) {
        cudaFuncSetAttribute(k1_qk,  cudaFuncAttributeMaxDynamicSharedMemorySize, K1_SMEM);
        cudaFuncSetAttribute(k2_mma, cudaFuncAttributeMaxDynamicSharedMemorySize, K2_SMEM);
        cudaFuncSetAttribute(k4_out, cudaFuncAttributeMaxDynamicSharedMemorySize, K4_SMEM);
        attr_set = true;
    }

    k1_qk<<<dim3(NN / 128, BB), 256, K1_SMEM>>>(x, wq, bq, wk, bk);
    k2_mma<<<dim3(CC / 128, BB, K2_NS), 256, K2_SMEM>>>(x);
    k2b_msum<<<129, 256>>>();
    k3_mma<<<dim3(CC / 128, BB, K3_CS), 256>>>(wv);
    k3c_merge<<<256, 256>>>(bv);
    k4_out<<<dim3(CC / 128, NN / 128, BB), 256, K4_SMEM>>>(x, gamma, out);
}

// round 8
// speedup vs baseline: 1.0690x; 1.0011x over previous
#include <cuda_runtime.h>
#include <cuda_bf16.h>
#include <cstdint>

// Problem constants (fixed by the dataset)
#define BB 8
#define CC 512
#define NN 4096
#define DD 64
#define K2_NS 8   // n-splits for k2
#define K3_CS 8   // c-splits for k3

// Scratch (static device globals — no allocation)
__device__ float g_Qf[BB][DD][NN];          // delu(Q)  8 MB
__device__ float g_Kf[BB][DD][NN];          // delu(K)  8 MB
__device__ float g_Mp[K2_NS][BB][CC][DD];   // partial M^T: [ns][b][c][d]
__device__ float g_Msum[BB][CC][DD];        // summed M^T (1 MB)
__device__ float g_KVp[K3_CS][BB][DD][CC];  // partial KV (c-splits)
__device__ float g_KV[BB][DD][CC];          // KV = M @ wv^T + Ksum (x) bv
__device__ float g_Ksp[32][BB][DD];         // per-n-tile Ksum partials (from k1)
__device__ float g_Ksum[BB][DD];

__device__ __forceinline__ float delu_f(float v) {
    return 10.0f * fmaxf(v, 0.0f) + __expf(10.0f * fminf(v, 0.0f));
}

__device__ __forceinline__ uint32_t smem_u32(const void* p) {
    uint32_t a;
    asm("{ .reg .u64 t; cvta.to.shared.u64 t, %1; cvt.u32.u64 %0, t; }"
        : "=r"(a) : "l"(p));
    return a;
}

#define CP16(dst, src) \
    asm volatile("cp.async.cg.shared.global [%0], [%1], 16;" :: "r"(dst), "l"(src))
#define CP_COMMIT() asm volatile("cp.async.commit_group;" ::: "memory")
#define CP_WAIT1()  asm volatile("cp.async.wait_group 1;" ::: "memory")
#define CP_WAIT0()  asm volatile("cp.async.wait_group 0;" ::: "memory")

// D += A(16x8) * B(8x8), tf32 inputs (fp32 bits, HW-truncated), f32 accum
__device__ __forceinline__ void mma_tf32(float4& d,
                                         uint32_t a0, uint32_t a1, uint32_t a2, uint32_t a3,
                                         uint32_t b0, uint32_t b1) {
    asm volatile(
        "mma.sync.aligned.m16n8k8.row.col.f32.tf32.tf32.f32 "
        "{%0,%1,%2,%3}, {%4,%5,%6,%7}, {%8,%9}, {%0,%1,%2,%3};"
        : "+f"(d.x), "+f"(d.y), "+f"(d.z), "+f"(d.w)
        : "r"(a0), "r"(a1), "r"(a2), "r"(a3), "r"(b0), "r"(b1));
}

// ---------------------------------------------------------------------------
// K1 (mma + cp.async 2-stage): [Wq;Wk](128x512) @ x[b](512x4096) + bias, delu
// Also emits per-block Ksum partials.
// ---------------------------------------------------------------------------
#define K1_ABUF (128 * 36)
#define K1_BBUF (32 * 136)
#define K1_SMEM ((2 * K1_ABUF + 2 * K1_BBUF) * 4)

__global__ __launch_bounds__(256) void k1_qk(
    const float* __restrict__ x,
    const float* __restrict__ wq, const float* __restrict__ bq,
    const float* __restrict__ wk, const float* __restrict__ bk)
{
    const int b  = blockIdx.y;
    const int n0 = blockIdx.x * 128;
    const int tid = threadIdx.x;
    const int wid = tid >> 5, lane = tid & 31;
    const int g = lane >> 2, tig = lane & 3;
    const int wm0 = (wid >> 1) * 32;
    const int wn0 = (wid & 1) * 64;

    extern __shared__ float dsm[];
    float* sA = dsm;
    float* sB = dsm + 2 * K1_ABUF;
    const uint32_t sA_addr = smem_u32(sA);
    const uint32_t sB_addr = smem_u32(sB);
    const uint32_t* sAu = reinterpret_cast<const uint32_t*>(sA);
    const uint32_t* sBu = reinterpret_cast<const uint32_t*>(sB);
    __shared__ float sKpart[64][2];   // [k-row][n-half]

    float4 acc[2][8];
#pragma unroll
    for (int i = 0; i < 2; i++)
#pragma unroll
        for (int j = 0; j < 8; j++) acc[i][j] = make_float4(0.f, 0.f, 0.f, 0.f);

#define K1_ISSUE(ch) do {                                                        \
    const int k0_ = (ch) * 32; const int buf_ = (ch) & 1;                        \
    _Pragma("unroll")                                                            \
    for (int i = 0; i < 4; i++) {                                                \
        int idx = tid + i * 256;                                                 \
        int r = idx >> 3; int kk = (idx & 7) << 2;                               \
        const float* src = (r < 64) ? (wq + (size_t)r * CC + k0_ + kk)           \
                                    : (wk + (size_t)(r - 64) * CC + k0_ + kk);   \
        CP16(sA_addr + (uint32_t)(buf_ * K1_ABUF + r * 36 + kk) * 4, src);       \
    }                                                                            \
    _Pragma("unroll")                                                            \
    for (int i = 0; i < 4; i++) {                                                \
        int idx = tid + i * 256;                                                 \
        int kk = idx >> 5; int j = (idx & 31) << 2;                              \
        const float* src = x + ((size_t)(b * CC + k0_ + kk)) * NN + n0 + j;      \
        CP16(sB_addr + (uint32_t)(buf_ * K1_BBUF + kk * 136 + j) * 4, src);      \
    }                                                                            \
    CP_COMMIT();                                                                 \
} while (0)

    K1_ISSUE(0);
    for (int ch = 0; ch < 16; ch++) {
        if (ch < 15) { K1_ISSUE(ch + 1); CP_WAIT1(); } else { CP_WAIT0(); }
        __syncthreads();
        const uint32_t* A = sAu + (ch & 1) * K1_ABUF;
        const uint32_t* Bm = sBu + (ch & 1) * K1_BBUF;
#pragma unroll
        for (int ks = 0; ks < 32; ks += 8) {
            uint32_t a[2][4];
#pragma unroll
            for (int i = 0; i < 2; i++) {
                int r = wm0 + i * 16 + g;
                a[i][0] = A[r * 36 + ks + tig];
                a[i][1] = A[(r + 8) * 36 + ks + tig];
                a[i][2] = A[r * 36 + ks + tig + 4];
                a[i][3] = A[(r + 8) * 36 + ks + tig + 4];
            }
#pragma unroll
            for (int j = 0; j < 8; j++) {
                int n = wn0 + j * 8 + g;
                uint32_t b0 = Bm[(ks + tig) * 136 + n];
                uint32_t b1 = Bm[(ks + tig + 4) * 136 + n];
#pragma unroll
                for (int i = 0; i < 2; i++)
                    mma_tf32(acc[i][j], a[i][0], a[i][1], a[i][2], a[i][3], b0, b1);
            }
        }
        __syncthreads();
    }

    // epilogue: bias + delu -> Qf / Kf, plus Ksum partials for K rows
    float psum[2][2] = {{0.f, 0.f}, {0.f, 0.f}};
#pragma unroll
    for (int i = 0; i < 2; i++) {
        int r0 = wm0 + i * 16 + g;
        int r1 = r0 + 8;
        float bias0 = (r0 < 64) ? bq[r0] : bk[r0 - 64];
        float bias1 = (r1 < 64) ? bq[r1] : bk[r1 - 64];
        float* dst0 = (r0 < 64) ? &g_Qf[b][r0][0] : &g_Kf[b][r0 - 64][0];
        float* dst1 = (r1 < 64) ? &g_Qf[b][r1][0] : &g_Kf[b][r1 - 64][0];
#pragma unroll
        for (int j = 0; j < 8; j++) {
            int n = n0 + wn0 + j * 8 + 2 * tig;
            float2 o0 = make_float2(delu_f(acc[i][j].x + bias0), delu_f(acc[i][j].y + bias0));
            float2 o1 = make_float2(delu_f(acc[i][j].z + bias1), delu_f(acc[i][j].w + bias1));
            *reinterpret_cast<float2*>(dst0 + n) = o0;
            *reinterpret_cast<float2*>(dst1 + n) = o1;
            psum[i][0] += o0.x + o0.y;
            psum[i][1] += o1.x + o1.y;
        }
    }
#pragma unroll
    for (int i = 0; i < 2; i++)
#pragma unroll
        for (int h = 0; h < 2; h++) {
            psum[i][h] += __shfl_xor_sync(0xffffffffu, psum[i][h], 1);
            psum[i][h] += __shfl_xor_sync(0xffffffffu, psum[i][h], 2);
        }
    if (tig == 0 && wm0 >= 64) {
#pragma unroll
        for (int i = 0; i < 2; i++) {
            int r0 = wm0 + i * 16 + g;
            sKpart[r0 - 64][wid & 1] = psum[i][0];
            sKpart[r0 - 64 + 8][wid & 1] = psum[i][1];
        }
    }
    __syncthreads();
    if (tid < 64)
        g_Ksp[blockIdx.x][b][tid] = sKpart[tid][0] + sKpart[tid][1];
}

// ---------------------------------------------------------------------------
// K2 (mma + cp.async 2-stage): Mp[ns][b][c][d] = sum_n x[b][c][n]*Kf[b][d][n]
// ---------------------------------------------------------------------------
#define K2_XBUF (128 * 36)
#define K2_KBUF (64 * 36)
#define K2_SMEM ((2 * K2_XBUF + 2 * K2_KBUF) * 4)

__global__ __launch_bounds__(256) void k2_mma(const float* __restrict__ x)
{
    const int b  = blockIdx.y;
    const int c0 = blockIdx.x * 128;
    const int ns = blockIdx.z;
    const int nbase = ns * (NN / K2_NS);       // 512 per split
    const int tid = threadIdx.x;
    const int wid = tid >> 5, lane = tid & 31;
    const int g = lane >> 2, tig = lane & 3;
    const int wc0 = (wid >> 1) * 32;
    const int wd0 = (wid & 1) * 32;

    extern __shared__ float dsm[];
    float* sX = dsm;
    float* sK = dsm + 2 * K2_XBUF;
    const uint32_t sX_addr = smem_u32(sX);
    const uint32_t sK_addr = smem_u32(sK);
    const uint32_t* sXu = reinterpret_cast<const uint32_t*>(sX);
    const uint32_t* sKu = reinterpret_cast<const uint32_t*>(sK);

    float4 acc[2][4];
#pragma unroll
    for (int i = 0; i < 2; i++)
#pragma unroll
        for (int j = 0; j < 4; j++) acc[i][j] = make_float4(0.f, 0.f, 0.f, 0.f);

#define K2_ISSUE(ch) do {                                                        \
    const int nb_ = nbase + (ch) * 32; const int buf_ = (ch) & 1;                \
    _Pragma("unroll")                                                            \
    for (int i = 0; i < 4; i++) {                                                \
        int idx = tid + i * 256;                                                 \
        int r = idx >> 3; int kk = (idx & 7) << 2;                               \
        const float* src = x + ((size_t)(b * CC + c0 + r)) * NN + nb_ + kk;      \
        CP16(sX_addr + (uint32_t)(buf_ * K2_XBUF + r * 36 + kk) * 4, src);       \
    }                                                                            \
    _Pragma("unroll")                                                            \
    for (int i = 0; i < 2; i++) {                                                \
        int idx = tid + i * 256;                                                 \
        int r = idx >> 3; int kk = (idx & 7) << 2;                               \
        const float* src = &g_Kf[b][r][nb_ + kk];                                \
        CP16(sK_addr + (uint32_t)(buf_ * K2_KBUF + r * 36 + kk) * 4, src);       \
    }                                                                            \
    CP_COMMIT();                                                                 \
} while (0)

    K2_ISSUE(0);
    for (int ch = 0; ch < 16; ch++) {
        if (ch < 15) { K2_ISSUE(ch + 1); CP_WAIT1(); } else { CP_WAIT0(); }
        __syncthreads();
        const uint32_t* X = sXu + (ch & 1) * K2_XBUF;
        const uint32_t* Km = sKu + (ch & 1) * K2_KBUF;
#pragma unroll
        for (int ks = 0; ks < 32; ks += 8) {
            uint32_t a[2][4];
#pragma unroll
            for (int i = 0; i < 2; i++) {
                int r = wc0 + i * 16 + g;
                a[i][0] = X[r * 36 + ks + tig];
                a[i][1] = X[(r + 8) * 36 + ks + tig];
                a[i][2] = X[r * 36 + ks + tig + 4];
                a[i][3] = X[(r + 8) * 36 + ks + tig + 4];
            }
#pragma unroll
            for (int j = 0; j < 4; j++) {
                int d = wd0 + j * 8 + g;
                uint32_t b0 = Km[d * 36 + ks + tig];
                uint32_t b1 = Km[d * 36 + ks + tig + 4];
#pragma unroll
                for (int i = 0; i < 2; i++)
                    mma_tf32(acc[i][j], a[i][0], a[i][1], a[i][2], a[i][3], b0, b1);
            }
        }
        __syncthreads();
    }
#pragma unroll
    for (int i = 0; i < 2; i++) {
        int r0 = c0 + wc0 + i * 16 + g;
#pragma unroll
        for (int j = 0; j < 4; j++) {
            int d = wd0 + j * 8 + 2 * tig;
            *reinterpret_cast<float2*>(&g_Mp[ns][b][r0][d])     = make_float2(acc[i][j].x, acc[i][j].y);
            *reinterpret_cast<float2*>(&g_Mp[ns][b][r0 + 8][d]) = make_float2(acc[i][j].z, acc[i][j].w);
        }
    }
}

// ---------------------------------------------------------------------------
// K2b: Msum = sum_ns Mp (blocks 0..127, 2 float4/thread), Ksum (block 128)
// ---------------------------------------------------------------------------
__global__ __launch_bounds__(256) void k2b_msum()
{
    if (blockIdx.x == 128) {
        for (int t = threadIdx.x; t < BB * DD; t += 256) {
            const int b = t >> 6, d = t & 63;
            float s = 0.f;
#pragma unroll
            for (int nb = 0; nb < 32; nb++) s += g_Ksp[nb][b][d];
            g_Ksum[b][d] = s;
        }
        return;
    }
    const float4* src = reinterpret_cast<const float4*>(g_Mp);
    float4* dst = reinterpret_cast<float4*>(g_Msum);
    const int f0 = blockIdx.x * 256 + threadIdx.x;   // two elements: f0, f0+32768
#pragma unroll
    for (int h = 0; h < 2; h++) {
        const int f = f0 + h * 32768;                // 0..65535 over b*c*d/4
        float4 s = make_float4(0.f, 0.f, 0.f, 0.f);
#pragma unroll
        for (int ns = 0; ns < K2_NS; ns++) {
            float4 v = src[(size_t)ns * 65536 + f];
            s.x += v.x; s.y += v.y; s.z += v.z; s.w += v.w;
        }
        dst[f] = s;
    }
}

// ---------------------------------------------------------------------------
// K3 (mma): KVp[cs][b][m][e] = sum_{c in 64-split} Msum[b][c][m] * wv[e][c]
// grid (4 e-tiles, 8 b, 8 cs) = 256 blocks, 256 thr. Tile 64m x 128e, K=64.
// ---------------------------------------------------------------------------
__global__ __launch_bounds__(256) void k3_mma(const float* __restrict__ wv)
{
    const int b  = blockIdx.y;
    const int e0 = blockIdx.x * 128;
    const int cs = blockIdx.z;
    const int cb0 = cs * 64;
    const int tid = threadIdx.x;
    const int wid = tid >> 5, lane = tid & 31;
    const int g = lane >> 2, tig = lane & 3;
    const int wm0 = (wid >> 2) * 32;   // 2 m-warps
    const int we0 = (wid & 3) * 32;    // 4 e-warps

    __shared__ float sM[32 * 72];      // [c][m] stride 72
    __shared__ float sW[128 * 36];     // [e][c] stride 36
    const uint32_t* sMu = reinterpret_cast<const uint32_t*>(sM);
    const uint32_t* sWu = reinterpret_cast<const uint32_t*>(sW);

    float4 acc[2][4];
#pragma unroll
    for (int i = 0; i < 2; i++)
#pragma unroll
        for (int j = 0; j < 4; j++) acc[i][j] = make_float4(0.f, 0.f, 0.f, 0.f);

#pragma unroll
    for (int cc = 0; cc < 64; cc += 32) {
        const int ca = cb0 + cc;
        // Msum tile: 32 c x 64 m = 512 float4
#pragma unroll
        for (int i = 0; i < 2; i++) {
            int idx = tid + i * 256;
            int c = idx >> 4;
            int m = (idx & 15) << 2;
            float4 v = *reinterpret_cast<const float4*>(&g_Msum[b][ca + c][m]);
            *reinterpret_cast<float4*>(&sM[c * 72 + m]) = v;
        }
        // wv tile: 128 e x 32 c = 1024 float4
#pragma unroll
        for (int i = 0; i < 4; i++) {
            int idx = tid + i * 256;
            int e = idx >> 3;
            int k = (idx & 7) << 2;
            float4 v = *reinterpret_cast<const float4*>(
                wv + (size_t)(e0 + e) * CC + ca + k);
            *reinterpret_cast<float4*>(&sW[e * 36 + k]) = v;
        }
        __syncthreads();
#pragma unroll
        for (int ks = 0; ks < 32; ks += 8) {
            uint32_t a[2][4];
#pragma unroll
            for (int i = 0; i < 2; i++) {
                int r = wm0 + i * 16 + g;
                a[i][0] = sMu[(ks + tig) * 72 + r];
                a[i][1] = sMu[(ks + tig) * 72 + r + 8];
                a[i][2] = sMu[(ks + tig + 4) * 72 + r];
                a[i][3] = sMu[(ks + tig + 4) * 72 + r + 8];
            }
#pragma unroll
            for (int j = 0; j < 4; j++) {
                int e = we0 + j * 8 + g;
                uint32_t b0 = sWu[e * 36 + ks + tig];
                uint32_t b1 = sWu[e * 36 + ks + tig + 4];
#pragma unroll
                for (int i = 0; i < 2; i++)
                    mma_tf32(acc[i][j], a[i][0], a[i][1], a[i][2], a[i][3], b0, b1);
            }
        }
        __syncthreads();
    }
#pragma unroll
    for (int i = 0; i < 2; i++) {
        int m0 = wm0 + i * 16 + g;
#pragma unroll
        for (int j = 0; j < 4; j++) {
            int e = e0 + we0 + j * 8 + 2 * tig;
            *reinterpret_cast<float2*>(&g_KVp[cs][b][m0][e])     = make_float2(acc[i][j].x, acc[i][j].y);
            *reinterpret_cast<float2*>(&g_KVp[cs][b][m0 + 8][e]) = make_float2(acc[i][j].z, acc[i][j].w);
        }
    }
}

// ---------------------------------------------------------------------------
// K3c: KV = sum_cs KVp + Ksum (x) bv.  64K float4; grid 256 x 256
// ---------------------------------------------------------------------------
__global__ __launch_bounds__(256) void k3c_merge(const float* __restrict__ bv)
{
    const int f = blockIdx.x * 256 + threadIdx.x;
    const int b = f >> 13;
    const int r = f & 8191;
    const int m = r >> 7;
    const int e4 = (r & 127) << 2;

    float4 s = make_float4(0.f, 0.f, 0.f, 0.f);
#pragma unroll
    for (int cs = 0; cs < K3_CS; cs++) {
        float4 v = *reinterpret_cast<const float4*>(&g_KVp[cs][b][m][e4]);
        s.x += v.x; s.y += v.y; s.z += v.z; s.w += v.w;
    }
    float4 bb = *reinterpret_cast<const float4*>(bv + e4);
    const float ks = g_Ksum[b][m];
    float4 o;
    o.x = s.x + ks * bb.x;
    o.y = s.y + ks * bb.y;
    o.z = s.z + ks * bb.z;
    o.w = s.w + ks * bb.w;
    *reinterpret_cast<float4*>(&g_KV[b][m][e4]) = o;
}

// ---------------------------------------------------------------------------
// K4 (mma + cp.async prefetch): out = x + gamma * norm[n] * (Qf^T @ KV)^T
// grid (4 c-tiles, 32 n-tiles, 8 b) — c fastest for Qf L2 reuse.
// ---------------------------------------------------------------------------
#define K4_QV (64 * 136)
#define K4_SMEM ((2 * K4_QV + 128 * 128) * 4)

__global__ __launch_bounds__(256) void k4_out(
    const float* __restrict__ x, const float* __restrict__ gamma,
    float* __restrict__ out)
{
    const int b  = blockIdx.z;
    const int c0 = blockIdx.x * 128;
    const int n0 = blockIdx.y * 128;
    const int tid = threadIdx.x;
    const int wid = tid >> 5, lane = tid & 31;
    const int g = lane >> 2, tig = lane & 3;
    const int wc0 = (wid >> 1) * 32;
    const int wn0 = (wid & 1) * 64;

    extern __shared__ float smem[];
    float* sQ = smem;                  // [d][n] stride 136
    float* sV = smem + K4_QV;          // [d][c] stride 136
    float* sX = smem + 2 * K4_QV;      // [c][n] 128x128
    const uint32_t sQ_addr = smem_u32(sQ);
    const uint32_t sV_addr = smem_u32(sV);
    const uint32_t sX_addr = smem_u32(sX);
    const uint32_t* sQu = reinterpret_cast<const uint32_t*>(sQ);
    const uint32_t* sVu = reinterpret_cast<const uint32_t*>(sV);
    __shared__ float snorm[128];
    __shared__ float sKs[64];

    // group 0: Qf + KV tiles
#pragma unroll
    for (int i = 0; i < 8; i++) {
        int idx = tid + i * 256;
        int d = idx >> 5;
        int j = (idx & 31) << 2;
        CP16(sQ_addr + (uint32_t)(d * 136 + j) * 4, &g_Qf[b][d][n0 + j]);
    }
#pragma unroll
    for (int i = 0; i < 8; i++) {
        int idx = tid + i * 256;
        int d = idx >> 5;
        int j = (idx & 31) << 2;
        CP16(sV_addr + (uint32_t)(d * 136 + j) * 4, &g_KV[b][d][c0 + j]);
    }
    CP_COMMIT();
    // group 1: x tile (consumed only in epilogue)
#pragma unroll
    for (int i = 0; i < 16; i++) {
        int idx = tid + i * 256;
        int c = idx >> 5;
        int j = (idx & 31) << 2;
        CP16(sX_addr + (uint32_t)(c * 128 + j) * 4,
             x + ((size_t)(b * CC + c0 + c)) * NN + n0 + j);
    }
    CP_COMMIT();

    if (tid < 64) sKs[tid] = g_Ksum[b][tid] + 1e-10f;
    CP_WAIT1();            // Qf + KV ready; x still in flight
    __syncthreads();

    // norm: 2 threads per n (d-halves), combined via shfl
    {
        int n = tid >> 1, h = tid & 1;
        float s = 0.f;
#pragma unroll
        for (int d = 0; d < 32; d++) s += sQ[(h * 32 + d) * 136 + n] * sKs[h * 32 + d];
        s += __shfl_xor_sync(0xffffffffu, s, 1);
        if (h == 0) snorm[n] = 1.0f / s;
    }
    __syncthreads();

    float4 acc[2][8];
#pragma unroll
    for (int i = 0; i < 2; i++)
#pragma unroll
        for (int j = 0; j < 8; j++) acc[i][j] = make_float4(0.f, 0.f, 0.f, 0.f);

#pragma unroll
    for (int ks = 0; ks < 64; ks += 8) {
        uint32_t a[2][4];
#pragma unroll
        for (int i = 0; i < 2; i++) {
            int r = wc0 + i * 16 + g;
            a[i][0] = sVu[(ks + tig) * 136 + r];
            a[i][1] = sVu[(ks + tig) * 136 + r + 8];
            a[i][2] = sVu[(ks + tig + 4) * 136 + r];
            a[i][3] = sVu[(ks + tig + 4) * 136 + r + 8];
        }
#pragma unroll
        for (int j = 0; j < 8; j++) {
            int n = wn0 + j * 8 + g;
            uint32_t b0 = sQu[(ks + tig) * 136 + n];
            uint32_t b1 = sQu[(ks + tig + 4) * 136 + n];
#pragma unroll
            for (int i = 0; i < 2; i++)
                mma_tf32(acc[i][j], a[i][0], a[i][1], a[i][2], a[i][3], b0, b1);
        }
    }

    CP_WAIT0();
    __syncthreads();

    const float gm = gamma[0];
#pragma unroll
    for (int i = 0; i < 2; i++) {
        int cl0 = wc0 + i * 16 + g;
        int cl1 = cl0 + 8;
#pragma unroll
        for (int j = 0; j < 8; j++) {
            int nl = wn0 + j * 8 + 2 * tig;
            float nm0 = snorm[nl], nm1 = snorm[nl + 1];
            float2 x0 = *reinterpret_cast<const float2*>(&sX[cl0 * 128 + nl]);
            float2 x1 = *reinterpret_cast<const float2*>(&sX[cl1 * 128 + nl]);
            size_t off0 = ((size_t)b * CC + c0 + cl0) * NN + n0 + nl;
            size_t off1 = ((size_t)b * CC + c0 + cl1) * NN + n0 + nl;
            float2 o0 = make_float2(x0.x + gm * acc[i][j].x * nm0,
                                    x0.y + gm * acc[i][j].y * nm1);
            float2 o1 = make_float2(x1.x + gm * acc[i][j].z * nm0,
                                    x1.y + gm * acc[i][j].w * nm1);
            *reinterpret_cast<float2*>(out + off0) = o0;
            *reinterpret_cast<float2*>(out + off1) = o1;
        }
    }
}

// ---------------------------------------------------------------------------
extern "C" void kernel_launch(void* const* d_in, const int* in_sizes, int n_in,
                              void* d_out, int out_size)
{
    const float* x     = (const float*)d_in[0];
    const float* wq    = (const float*)d_in[1];
    const float* bq    = (const float*)d_in[2];
    const float* wk    = (const float*)d_in[3];
    const float* bk    = (const float*)d_in[4];
    const float* wv    = (const float*)d_in[5];
    const float* bv    = (const float*)d_in[6];
    const float* gamma = (const float*)d_in[7];
    float* out = (float*)d_out;

    static bool attr_set = false;
    if (!attr_set) {
        cudaFuncSetAttribute(k1_qk,  cudaFuncAttributeMaxDynamicSharedMemorySize, K1_SMEM);
        cudaFuncSetAttribute(k2_mma, cudaFuncAttributeMaxDynamicSharedMemorySize, K2_SMEM);
        cudaFuncSetAttribute(k4_out, cudaFuncAttributeMaxDynamicSharedMemorySize, K4_SMEM);
        attr_set = true;
    }

    k1_qk<<<dim3(NN / 128, BB), 256, K1_SMEM>>>(x, wq, bq, wk, bk);
    k2_mma<<<dim3(CC / 128, BB, K2_NS), 256, K2_SMEM>>>(x);
    k2b_msum<<<129, 256>>>();
    k3_mma<<<dim3(CC / 128, BB, K3_CS), 256>>>(wv);
    k3c_merge<<<256, 256>>>(bv);
    k4_out<<<dim3(CC / 128, NN / 128, BB), 256, K4_SMEM>>>(x, gamma, out);
}